// round 3
// baseline (speedup 1.0000x reference)
#include <cuda_runtime.h>
#include <cstdint>

// ---------------------------------------------------------------------------
// PartBasedGraphCNN: conv3x3(3->32)+relu+pool2 -> grid-GCN(32->64) -> FC1 -> FC2
// fp32, packed f32x2 FMA. FC1 staged via cp.async.bulk (no LDGSTS issue tax).
// ---------------------------------------------------------------------------

#define K_FC 262144  // 4096 nodes * 64 feats

__device__ float d_pool_buf[32 * 32 * 64 * 64];     // [B][32][64][64]  16.8 MB
__device__ float d_g_buf[32u * 4096u * 64u];        // [B][N][64]       33.6 MB
__device__ float d_part_buf[296 * 32 * 128];        // [set][B][128]     4.9 MB
__device__ float d_f1_buf[32 * 128];                // [B][128]

__device__ __forceinline__ void fma2(float2 &d, const float2 a, const float2 b) {
    asm("fma.rn.f32x2 %0, %1, %2, %0;"
        : "+l"(*reinterpret_cast<unsigned long long *>(&d))
        : "l"(*reinterpret_cast<const unsigned long long *>(&a)),
          "l"(*reinterpret_cast<const unsigned long long *>(&b)));
}

__device__ __forceinline__ uint32_t s2u(const void *p) {
    return (uint32_t)__cvta_generic_to_shared(p);
}

__device__ __forceinline__ void bulk_cp(void *dst_smem, const void *src_gmem,
                                        uint32_t bytes, uint32_t mbar) {
    asm volatile(
        "cp.async.bulk.shared::cta.global.mbarrier::complete_tx::bytes "
        "[%0], [%1], %2, [%3];"
        :: "r"(s2u(dst_smem)), "l"(src_gmem), "r"(bytes), "r"(mbar) : "memory");
}

__device__ __forceinline__ void mbar_init(uint32_t mbar, uint32_t count) {
    asm volatile("mbarrier.init.shared::cta.b64 [%0], %1;" :: "r"(mbar), "r"(count));
}

__device__ __forceinline__ void mbar_expect_tx(uint32_t mbar, uint32_t bytes) {
    asm volatile("mbarrier.arrive.expect_tx.shared::cta.b64 _, [%0], %1;"
                 :: "r"(mbar), "r"(bytes) : "memory");
}

__device__ __forceinline__ void mbar_wait(uint32_t mbar, uint32_t parity) {
    asm volatile(
        "{\n\t"
        ".reg .pred P;\n\t"
        "WAIT_%=:\n\t"
        "mbarrier.try_wait.parity.acquire.cta.shared::cta.b64 P, [%0], %1, 0x989680;\n\t"
        "@P bra.uni DONE_%=;\n\t"
        "bra.uni WAIT_%=;\n\t"
        "DONE_%=:\n\t"
        "}"
        :: "r"(mbar), "r"(parity) : "memory");
}

// ---------------------------------------------------------------------------
// Kernel 1: conv 3x3 SAME + bias + relu + maxpool 2x2  (unchanged)
// ---------------------------------------------------------------------------
__global__ void __launch_bounds__(256) conv_pool_kernel(
    const float *__restrict__ x, const float *__restrict__ cw,
    const float *__restrict__ cb)
{
    __shared__ float sin_[3][34][34];
    __shared__ float wp[27 * 32];
    __shared__ float bb[32];

    int t = threadIdx.x;
    int b = blockIdx.y;
    int tpy = (blockIdx.x >> 2) * 16, tpx = (blockIdx.x & 3) * 16;

    for (int i = t; i < 864; i += 256) {
        int co = i / 27, rem = i % 27;
        wp[rem * 32 + co] = cw[i];
    }
    if (t < 32) bb[t] = cb[t];

    int oy = 2 * tpy - 1, ox = 2 * tpx - 1;
    for (int i = t; i < 3 * 34 * 34; i += 256) {
        int ci = i / 1156, rem = i % 1156, iy = rem / 34, ix = rem % 34;
        int gy = oy + iy, gx = ox + ix;
        float v = 0.f;
        if (gy >= 0 && gy < 128 && gx >= 0 && gx < 128)
            v = x[((b * 3 + ci) * 128 + gy) * 128 + gx];
        sin_[ci][iy][ix] = v;
    }
    __syncthreads();

    int py = t >> 4, px = t & 15;
    float in[3][4][4];
#pragma unroll
    for (int ci = 0; ci < 3; ci++)
#pragma unroll
        for (int r = 0; r < 4; r++)
#pragma unroll
            for (int c = 0; c < 4; c++)
                in[ci][r][c] = sin_[ci][2 * py + r][2 * px + c];

    const float2 *wp2 = reinterpret_cast<const float2 *>(wp);
    int gy = tpy + py, gx = tpx + px;
    float *outb = d_pool_buf + (size_t)b * 131072;

#pragma unroll
    for (int g = 0; g < 4; g++) {
        float2 acc[2][2][4];
#pragma unroll
        for (int dy = 0; dy < 2; dy++)
#pragma unroll
            for (int dx = 0; dx < 2; dx++)
#pragma unroll
                for (int p = 0; p < 4; p++) acc[dy][dx][p] = make_float2(0.f, 0.f);

#pragma unroll
        for (int ci = 0; ci < 3; ci++)
#pragma unroll
            for (int ky = 0; ky < 3; ky++)
#pragma unroll
                for (int kx = 0; kx < 3; kx++) {
                    int tap = ci * 9 + ky * 3 + kx;
                    float2 w0 = wp2[tap * 16 + g * 4 + 0];
                    float2 w1 = wp2[tap * 16 + g * 4 + 1];
                    float2 w2 = wp2[tap * 16 + g * 4 + 2];
                    float2 w3 = wp2[tap * 16 + g * 4 + 3];
#pragma unroll
                    for (int dy = 0; dy < 2; dy++)
#pragma unroll
                        for (int dx = 0; dx < 2; dx++) {
                            float iv = in[ci][dy + ky][dx + kx];
                            float2 iv2 = make_float2(iv, iv);
                            fma2(acc[dy][dx][0], iv2, w0);
                            fma2(acc[dy][dx][1], iv2, w1);
                            fma2(acc[dy][dx][2], iv2, w2);
                            fma2(acc[dy][dx][3], iv2, w3);
                        }
                }
#pragma unroll
        for (int p = 0; p < 4; p++) {
            int co = g * 8 + p * 2;
            float mx = fmaxf(fmaxf(acc[0][0][p].x, acc[0][1][p].x),
                             fmaxf(acc[1][0][p].x, acc[1][1][p].x));
            float my = fmaxf(fmaxf(acc[0][0][p].y, acc[0][1][p].y),
                             fmaxf(acc[1][0][p].y, acc[1][1][p].y));
            mx = fmaxf(mx + bb[co], 0.f);
            my = fmaxf(my + bb[co + 1], 0.f);
            outb[(co * 64 + gy) * 64 + gx] = mx;
            outb[((co + 1) * 64 + gy) * 64 + gx] = my;
        }
    }
}

// ---------------------------------------------------------------------------
// Kernel 2: GCN (stencil on 32-dim feats, then x32->64 GEMM)  (unchanged)
// ---------------------------------------------------------------------------
__device__ __forceinline__ float dinvf(int r, int c) {
    int deg = 1 + (r > 0) + (r < 63) + (c > 0) + (c < 63);
    return rsqrtf((float)deg);
}

__global__ void __launch_bounds__(256) gcn_kernel(
    const float *__restrict__ gw, const float *__restrict__ gb)
{
    extern __shared__ float sm[];
    float *aggx = sm;            // [512][36]
    float *wg = sm + 512 * 36;   // [32][64]
    float *bg = wg + 2048;       // [64]

    int t = threadIdx.x, b = blockIdx.y;
    int node0 = blockIdx.x * 512;

    for (int i = t; i < 2048; i += 256) wg[i] = gw[i];
    if (t < 64) bg[t] = gb[t];

    const float *nf = d_pool_buf + (size_t)b * 131072;
    int q = t & 7, ns = t >> 3;
#pragma unroll 4
    for (int i = 0; i < 16; i++) {
        int nl = ns + 32 * i;
        int n = node0 + nl;
        int r = n >> 6, c = n & 63;
        float dn = dinvf(r, c);
        const float4 *base = reinterpret_cast<const float4 *>(nf) + n * 8 + q;
        float4 v = __ldg(base);
        float4 a;
        a.x = dn * v.x; a.y = dn * v.y; a.z = dn * v.z; a.w = dn * v.w;
        if (r > 0) {
            float s = dinvf(r - 1, c); float4 u = __ldg(base - 512);
            a.x += s * u.x; a.y += s * u.y; a.z += s * u.z; a.w += s * u.w;
        }
        if (r < 63) {
            float s = dinvf(r + 1, c); float4 u = __ldg(base + 512);
            a.x += s * u.x; a.y += s * u.y; a.z += s * u.z; a.w += s * u.w;
        }
        if (c > 0) {
            float s = dinvf(r, c - 1); float4 u = __ldg(base - 8);
            a.x += s * u.x; a.y += s * u.y; a.z += s * u.z; a.w += s * u.w;
        }
        if (c < 63) {
            float s = dinvf(r, c + 1); float4 u = __ldg(base + 8);
            a.x += s * u.x; a.y += s * u.y; a.z += s * u.z; a.w += s * u.w;
        }
        a.x *= dn; a.y *= dn; a.z *= dn; a.w *= dn;
        *reinterpret_cast<float4 *>(&aggx[nl * 36 + q * 4]) = a;
    }
    __syncthreads();

    int ot = t & 7, ng = t >> 3;
    const float4 *wg4 = reinterpret_cast<const float4 *>(wg);
    float *gout = d_g_buf + (size_t)b * 262144;
#pragma unroll
    for (int it = 0; it < 2; it++) {
        int nb = (it * 32 + ng) * 8;
        float2 acc[8][4];
#pragma unroll
        for (int i = 0; i < 8; i++)
#pragma unroll
            for (int p = 0; p < 4; p++) acc[i][p] = make_float2(0.f, 0.f);

#pragma unroll 4
        for (int f = 0; f < 32; f++) {
            float4 wA = wg4[f * 16 + ot * 2];
            float4 wB = wg4[f * 16 + ot * 2 + 1];
            float2 p0 = make_float2(wA.x, wA.y), p1 = make_float2(wA.z, wA.w);
            float2 p2 = make_float2(wB.x, wB.y), p3 = make_float2(wB.z, wB.w);
#pragma unroll
            for (int i = 0; i < 8; i++) {
                float av = aggx[(nb + i) * 36 + f];
                float2 ad = make_float2(av, av);
                fma2(acc[i][0], ad, p0);
                fma2(acc[i][1], ad, p1);
                fma2(acc[i][2], ad, p2);
                fma2(acc[i][3], ad, p3);
            }
        }
#pragma unroll
        for (int i = 0; i < 8; i++) {
            float2 *op = reinterpret_cast<float2 *>(
                gout + (size_t)(node0 + nb + i) * 64 + ot * 8);
#pragma unroll
            for (int p = 0; p < 4; p++) {
                float2 v;
                v.x = fmaxf(acc[i][p].x + bg[ot * 8 + 2 * p], 0.f);
                v.y = fmaxf(acc[i][p].y + bg[ot * 8 + 2 * p + 1], 0.f);
                op[p] = v;
            }
        }
    }
}

// ---------------------------------------------------------------------------
// Kernel 3: FC1. 296 blocks (1 wave, 2/SM), double-buffered cp.async.bulk
// stages of 64 k. Padded 272B rows -> conflict-free LDS.128 without swizzle.
// Thread tile 8j x 4b; fma2 accumulates over k pairs; one partial set/block.
// ---------------------------------------------------------------------------
#define FC1_ROW 68               // floats per padded row (272 B)
#define FC1_W_FLOATS (128 * FC1_ROW)
#define FC1_G_FLOATS (32 * FC1_ROW)
#define FC1_STAGE_BYTES 40960    // (128+32) rows * 256 B

__device__ __forceinline__ void fc1_issue_stage(
    float *Wd, float *Gd, uint32_t mbar,
    const float *__restrict__ w1, const float *__restrict__ g, int kglob, int t)
{
    // 32 issuing threads; each: 4 W rows + 1 G row = 5 x 256B = 1280 B
    mbar_expect_tx(mbar, 1280);
#pragma unroll
    for (int i = 0; i < 4; i++) {
        int row = t + 32 * i;
        bulk_cp(Wd + row * FC1_ROW, w1 + (size_t)row * K_FC + kglob, 256, mbar);
    }
    bulk_cp(Gd + t * FC1_ROW, g + (size_t)t * K_FC + kglob, 256, mbar);
}

__global__ void __launch_bounds__(128, 2) fc1_kernel(const float *__restrict__ w1)
{
    extern __shared__ float sm[];
    float *Wb[2] = {sm, sm + FC1_W_FLOATS};
    float *Gb[2] = {sm + 2 * FC1_W_FLOATS, sm + 2 * FC1_W_FLOATS + FC1_G_FLOATS};
    __shared__ __align__(8) uint64_t mbar_s[2];
    uint32_t mb0 = s2u(&mbar_s[0]), mb1 = s2u(&mbar_s[1]);

    const float *g = d_g_buf;
    int t = threadIdx.x, bi = blockIdx.x;
    int jg = t & 15, bg = t >> 4;  // j = jg + 16*jj, b = bg + 8*bb

    int kstart, nst;
    if (bi < 248) { kstart = bi * 896; nst = 14; }
    else          { kstart = 222208 + (bi - 248) * 832; nst = 13; }

    if (t == 0) { mbar_init(mb0, 32); mbar_init(mb1, 32); }
    __syncthreads();

    if (t < 32) fc1_issue_stage(Wb[0], Gb[0], mb0, w1, g, kstart, t);

    float2 acc[8][4];
#pragma unroll
    for (int jj = 0; jj < 8; jj++)
#pragma unroll
        for (int bb = 0; bb < 4; bb++) acc[jj][bb] = make_float2(0.f, 0.f);

    for (int st = 0; st < nst; st++) {
        int slot = st & 1;
        if (st + 1 < nst && t < 32)
            fc1_issue_stage(Wb[slot ^ 1], Gb[slot ^ 1], slot ? mb0 : mb1,
                            w1, g, kstart + (st + 1) * 64, t);

        mbar_wait(slot ? mb1 : mb0, (st >> 1) & 1);

        const float *W = Wb[slot];
        const float *G = Gb[slot];
#pragma unroll 4
        for (int u = 0; u < 16; u++) {
            float4 g4[4];
#pragma unroll
            for (int bb = 0; bb < 4; bb++)
                g4[bb] = *reinterpret_cast<const float4 *>(
                    G + (bg + 8 * bb) * FC1_ROW + u * 4);
#pragma unroll
            for (int jj = 0; jj < 8; jj++) {
                float4 w4 = *reinterpret_cast<const float4 *>(
                    W + (jg + 16 * jj) * FC1_ROW + u * 4);
                float2 wl = make_float2(w4.x, w4.y);
                float2 wh = make_float2(w4.z, w4.w);
#pragma unroll
                for (int bb = 0; bb < 4; bb++) {
                    fma2(acc[jj][bb], make_float2(g4[bb].x, g4[bb].y), wl);
                    fma2(acc[jj][bb], make_float2(g4[bb].z, g4[bb].w), wh);
                }
            }
        }
        __syncthreads();
    }

    float *pp = d_part_buf + (size_t)bi * 4096;
#pragma unroll
    for (int bb = 0; bb < 4; bb++)
#pragma unroll
        for (int jj = 0; jj < 8; jj++)
            pp[(bg + 8 * bb) * 128 + jg + 16 * jj] = acc[jj][bb].x + acc[jj][bb].y;
}

// ---------------------------------------------------------------------------
// Kernel 4a: reduce 296 partial sets -> relu(f1 + b1).  grid (32 b, 4 jq)
// 1024 threads: 32 j-lanes x 32 set-groups.
// ---------------------------------------------------------------------------
__global__ void __launch_bounds__(1024) fc1_reduce_kernel(const float *__restrict__ f1b)
{
    __shared__ float red[32][33];
    int t = threadIdx.x, b = blockIdx.x, jq = blockIdx.y;
    int jl = t & 31, sg = t >> 5;
    int j = jq * 32 + jl;

    const float *pp = d_part_buf + b * 128 + j;
    float ssum = 0.f;
#pragma unroll 5
    for (int i = sg; i < 296; i += 32) ssum += pp[(size_t)i * 4096];
    red[sg][jl] = ssum;
    __syncthreads();

    if (t < 32) {
        float v = 0.f;
#pragma unroll
        for (int u = 0; u < 32; u++) v += red[u][t];
        int jo = jq * 32 + t;
        d_f1_buf[b * 128 + jo] = fmaxf(v + f1b[jo], 0.f);
    }
}

// ---------------------------------------------------------------------------
// Kernel 4b: FC2 (101 x 128) + bias.  grid 32 (one block per batch)
// ---------------------------------------------------------------------------
__global__ void __launch_bounds__(128) fc2_kernel(
    const float *__restrict__ w2, const float *__restrict__ b2,
    float *__restrict__ out)
{
    __shared__ float f1s[128];
    int t = threadIdx.x, b = blockIdx.x;
    f1s[t] = d_f1_buf[b * 128 + t];
    __syncthreads();

    if (t < 101) {
        float acc = b2[t];
        const float *wr = w2 + t * 128;
#pragma unroll 8
        for (int jj = 0; jj < 128; jj++) acc = fmaf(f1s[jj], __ldg(&wr[jj]), acc);
        out[b * 101 + t] = acc;
    }
}

// ---------------------------------------------------------------------------
extern "C" void kernel_launch(void *const *d_in, const int *in_sizes, int n_in,
                              void *d_out, int out_size)
{
    (void)in_sizes; (void)n_in; (void)out_size;
    const float *x  = (const float *)d_in[0];
    const float *cw = (const float *)d_in[1];
    const float *cb = (const float *)d_in[2];
    const float *gw = (const float *)d_in[3];
    const float *gb = (const float *)d_in[4];
    const float *w1 = (const float *)d_in[5];
    const float *b1 = (const float *)d_in[6];
    const float *w2 = (const float *)d_in[7];
    const float *b2 = (const float *)d_in[8];
    float *out = (float *)d_out;

    const int gcn_smem = (512 * 36 + 2048 + 64) * 4;               // 82176 B
    const int fc1_smem = (2 * FC1_W_FLOATS + 2 * FC1_G_FLOATS) * 4; // 87040 B
    cudaFuncSetAttribute(gcn_kernel, cudaFuncAttributeMaxDynamicSharedMemorySize, gcn_smem);
    cudaFuncSetAttribute(fc1_kernel, cudaFuncAttributeMaxDynamicSharedMemorySize, fc1_smem);

    conv_pool_kernel<<<dim3(16, 32), 256>>>(x, cw, cb);
    gcn_kernel<<<dim3(8, 32), 256, gcn_smem>>>(gw, gb);
    fc1_kernel<<<296, 128, fc1_smem>>>(w1);
    fc1_reduce_kernel<<<dim3(32, 4), 1024>>>(b1);
    fc2_kernel<<<32, 128>>>(w2, b2, out);
}

// round 4
// speedup vs baseline: 1.0209x; 1.0209x over previous
#include <cuda_runtime.h>
#include <cstdint>

// ---------------------------------------------------------------------------
// PartBasedGraphCNN: conv3x3(3->32)+relu+pool2 -> grid-GCN(32->64) -> FC1 -> FC2
// fp32, packed f32x2 FMA. FC1: cp.async.bulk staging, 8j x 8b tile, 2-way k-split.
// ---------------------------------------------------------------------------

#define K_FC 262144  // 4096 nodes * 64 feats

__device__ float d_pool_buf[32 * 32 * 64 * 64];     // [B][32][64][64]  16.8 MB
__device__ float d_g_buf[32u * 4096u * 64u];        // [B][N][64]       33.6 MB
__device__ float d_part_buf[592 * 32 * 128];        // [set][B][128]     9.7 MB
__device__ float d_f1_buf[32 * 128];                // [B][128]

__device__ __forceinline__ void fma2(float2 &d, const float2 a, const float2 b) {
    asm("fma.rn.f32x2 %0, %1, %2, %0;"
        : "+l"(*reinterpret_cast<unsigned long long *>(&d))
        : "l"(*reinterpret_cast<const unsigned long long *>(&a)),
          "l"(*reinterpret_cast<const unsigned long long *>(&b)));
}

__device__ __forceinline__ uint32_t s2u(const void *p) {
    return (uint32_t)__cvta_generic_to_shared(p);
}

__device__ __forceinline__ void bulk_cp(void *dst_smem, const void *src_gmem,
                                        uint32_t bytes, uint32_t mbar) {
    asm volatile(
        "cp.async.bulk.shared::cta.global.mbarrier::complete_tx::bytes "
        "[%0], [%1], %2, [%3];"
        :: "r"(s2u(dst_smem)), "l"(src_gmem), "r"(bytes), "r"(mbar) : "memory");
}

__device__ __forceinline__ void mbar_init(uint32_t mbar, uint32_t count) {
    asm volatile("mbarrier.init.shared::cta.b64 [%0], %1;" :: "r"(mbar), "r"(count));
}

__device__ __forceinline__ void mbar_expect_tx(uint32_t mbar, uint32_t bytes) {
    asm volatile("mbarrier.arrive.expect_tx.shared::cta.b64 _, [%0], %1;"
                 :: "r"(mbar), "r"(bytes) : "memory");
}

__device__ __forceinline__ void mbar_wait(uint32_t mbar, uint32_t parity) {
    asm volatile(
        "{\n\t"
        ".reg .pred P;\n\t"
        "WAIT_%=:\n\t"
        "mbarrier.try_wait.parity.acquire.cta.shared::cta.b64 P, [%0], %1, 0x989680;\n\t"
        "@P bra.uni DONE_%=;\n\t"
        "bra.uni WAIT_%=;\n\t"
        "DONE_%=:\n\t"
        "}"
        :: "r"(mbar), "r"(parity) : "memory");
}

// ---------------------------------------------------------------------------
// Kernel 1: conv 3x3 SAME + bias + relu + maxpool 2x2  (unchanged)
// ---------------------------------------------------------------------------
__global__ void __launch_bounds__(256) conv_pool_kernel(
    const float *__restrict__ x, const float *__restrict__ cw,
    const float *__restrict__ cb)
{
    __shared__ float sin_[3][34][34];
    __shared__ float wp[27 * 32];
    __shared__ float bb[32];

    int t = threadIdx.x;
    int b = blockIdx.y;
    int tpy = (blockIdx.x >> 2) * 16, tpx = (blockIdx.x & 3) * 16;

    for (int i = t; i < 864; i += 256) {
        int co = i / 27, rem = i % 27;
        wp[rem * 32 + co] = cw[i];
    }
    if (t < 32) bb[t] = cb[t];

    int oy = 2 * tpy - 1, ox = 2 * tpx - 1;
    for (int i = t; i < 3 * 34 * 34; i += 256) {
        int ci = i / 1156, rem = i % 1156, iy = rem / 34, ix = rem % 34;
        int gy = oy + iy, gx = ox + ix;
        float v = 0.f;
        if (gy >= 0 && gy < 128 && gx >= 0 && gx < 128)
            v = x[((b * 3 + ci) * 128 + gy) * 128 + gx];
        sin_[ci][iy][ix] = v;
    }
    __syncthreads();

    int py = t >> 4, px = t & 15;
    float in[3][4][4];
#pragma unroll
    for (int ci = 0; ci < 3; ci++)
#pragma unroll
        for (int r = 0; r < 4; r++)
#pragma unroll
            for (int c = 0; c < 4; c++)
                in[ci][r][c] = sin_[ci][2 * py + r][2 * px + c];

    const float2 *wp2 = reinterpret_cast<const float2 *>(wp);
    int gy = tpy + py, gx = tpx + px;
    float *outb = d_pool_buf + (size_t)b * 131072;

#pragma unroll
    for (int g = 0; g < 4; g++) {
        float2 acc[2][2][4];
#pragma unroll
        for (int dy = 0; dy < 2; dy++)
#pragma unroll
            for (int dx = 0; dx < 2; dx++)
#pragma unroll
                for (int p = 0; p < 4; p++) acc[dy][dx][p] = make_float2(0.f, 0.f);

#pragma unroll
        for (int ci = 0; ci < 3; ci++)
#pragma unroll
            for (int ky = 0; ky < 3; ky++)
#pragma unroll
                for (int kx = 0; kx < 3; kx++) {
                    int tap = ci * 9 + ky * 3 + kx;
                    float2 w0 = wp2[tap * 16 + g * 4 + 0];
                    float2 w1 = wp2[tap * 16 + g * 4 + 1];
                    float2 w2 = wp2[tap * 16 + g * 4 + 2];
                    float2 w3 = wp2[tap * 16 + g * 4 + 3];
#pragma unroll
                    for (int dy = 0; dy < 2; dy++)
#pragma unroll
                        for (int dx = 0; dx < 2; dx++) {
                            float iv = in[ci][dy + ky][dx + kx];
                            float2 iv2 = make_float2(iv, iv);
                            fma2(acc[dy][dx][0], iv2, w0);
                            fma2(acc[dy][dx][1], iv2, w1);
                            fma2(acc[dy][dx][2], iv2, w2);
                            fma2(acc[dy][dx][3], iv2, w3);
                        }
                }
#pragma unroll
        for (int p = 0; p < 4; p++) {
            int co = g * 8 + p * 2;
            float mx = fmaxf(fmaxf(acc[0][0][p].x, acc[0][1][p].x),
                             fmaxf(acc[1][0][p].x, acc[1][1][p].x));
            float my = fmaxf(fmaxf(acc[0][0][p].y, acc[0][1][p].y),
                             fmaxf(acc[1][0][p].y, acc[1][1][p].y));
            mx = fmaxf(mx + bb[co], 0.f);
            my = fmaxf(my + bb[co + 1], 0.f);
            outb[(co * 64 + gy) * 64 + gx] = mx;
            outb[((co + 1) * 64 + gy) * 64 + gx] = my;
        }
    }
}

// ---------------------------------------------------------------------------
// Kernel 2: GCN (stencil on 32-dim feats, then x32->64 GEMM)  (unchanged)
// ---------------------------------------------------------------------------
__device__ __forceinline__ float dinvf(int r, int c) {
    int deg = 1 + (r > 0) + (r < 63) + (c > 0) + (c < 63);
    return rsqrtf((float)deg);
}

__global__ void __launch_bounds__(256) gcn_kernel(
    const float *__restrict__ gw, const float *__restrict__ gb)
{
    extern __shared__ float sm[];
    float *aggx = sm;            // [512][36]
    float *wg = sm + 512 * 36;   // [32][64]
    float *bg = wg + 2048;       // [64]

    int t = threadIdx.x, b = blockIdx.y;
    int node0 = blockIdx.x * 512;

    for (int i = t; i < 2048; i += 256) wg[i] = gw[i];
    if (t < 64) bg[t] = gb[t];

    const float *nf = d_pool_buf + (size_t)b * 131072;
    int q = t & 7, ns = t >> 3;
#pragma unroll 4
    for (int i = 0; i < 16; i++) {
        int nl = ns + 32 * i;
        int n = node0 + nl;
        int r = n >> 6, c = n & 63;
        float dn = dinvf(r, c);
        const float4 *base = reinterpret_cast<const float4 *>(nf) + n * 8 + q;
        float4 v = __ldg(base);
        float4 a;
        a.x = dn * v.x; a.y = dn * v.y; a.z = dn * v.z; a.w = dn * v.w;
        if (r > 0) {
            float s = dinvf(r - 1, c); float4 u = __ldg(base - 512);
            a.x += s * u.x; a.y += s * u.y; a.z += s * u.z; a.w += s * u.w;
        }
        if (r < 63) {
            float s = dinvf(r + 1, c); float4 u = __ldg(base + 512);
            a.x += s * u.x; a.y += s * u.y; a.z += s * u.z; a.w += s * u.w;
        }
        if (c > 0) {
            float s = dinvf(r, c - 1); float4 u = __ldg(base - 8);
            a.x += s * u.x; a.y += s * u.y; a.z += s * u.z; a.w += s * u.w;
        }
        if (c < 63) {
            float s = dinvf(r, c + 1); float4 u = __ldg(base + 8);
            a.x += s * u.x; a.y += s * u.y; a.z += s * u.z; a.w += s * u.w;
        }
        a.x *= dn; a.y *= dn; a.z *= dn; a.w *= dn;
        *reinterpret_cast<float4 *>(&aggx[nl * 36 + q * 4]) = a;
    }
    __syncthreads();

    int ot = t & 7, ng = t >> 3;
    const float4 *wg4 = reinterpret_cast<const float4 *>(wg);
    float *gout = d_g_buf + (size_t)b * 262144;
#pragma unroll
    for (int it = 0; it < 2; it++) {
        int nb = (it * 32 + ng) * 8;
        float2 acc[8][4];
#pragma unroll
        for (int i = 0; i < 8; i++)
#pragma unroll
            for (int p = 0; p < 4; p++) acc[i][p] = make_float2(0.f, 0.f);

#pragma unroll 4
        for (int f = 0; f < 32; f++) {
            float4 wA = wg4[f * 16 + ot * 2];
            float4 wB = wg4[f * 16 + ot * 2 + 1];
            float2 p0 = make_float2(wA.x, wA.y), p1 = make_float2(wA.z, wA.w);
            float2 p2 = make_float2(wB.x, wB.y), p3 = make_float2(wB.z, wB.w);
#pragma unroll
            for (int i = 0; i < 8; i++) {
                float av = aggx[(nb + i) * 36 + f];
                float2 ad = make_float2(av, av);
                fma2(acc[i][0], ad, p0);
                fma2(acc[i][1], ad, p1);
                fma2(acc[i][2], ad, p2);
                fma2(acc[i][3], ad, p3);
            }
        }
#pragma unroll
        for (int i = 0; i < 8; i++) {
            float2 *op = reinterpret_cast<float2 *>(
                gout + (size_t)(node0 + nb + i) * 64 + ot * 8);
#pragma unroll
            for (int p = 0; p < 4; p++) {
                float2 v;
                v.x = fmaxf(acc[i][p].x + bg[ot * 8 + 2 * p], 0.f);
                v.y = fmaxf(acc[i][p].y + bg[ot * 8 + 2 * p + 1], 0.f);
                op[p] = v;
            }
        }
    }
}

// ---------------------------------------------------------------------------
// Dummy kernel: ensures fc1_kernel is the 4th launch (ncu profiles launch #4).
// ---------------------------------------------------------------------------
__global__ void nop_kernel() {}

// ---------------------------------------------------------------------------
// Kernel 3: FC1. 296 blocks (2/SM), double-buffered cp.async.bulk stages of
// 64 k. 2-way k-split: 64 threads per half, thread tile 8j x 8b.
// Per u: 16 LDS.128 : 128 fma2. Partial sets = 592 (2 per block).
// ---------------------------------------------------------------------------
#define FC1_ROW 68               // floats per padded row (272 B)
#define FC1_W_FLOATS (128 * FC1_ROW)
#define FC1_G_FLOATS (32 * FC1_ROW)

__device__ __forceinline__ void fc1_issue_stage(
    float *Wd, float *Gd, uint32_t mbar,
    const float *__restrict__ w1, const float *__restrict__ g, int kglob, int t)
{
    // 32 issuing threads; each: 4 W rows + 1 G row = 5 x 256B = 1280 B
    mbar_expect_tx(mbar, 1280);
#pragma unroll
    for (int i = 0; i < 4; i++) {
        int row = t + 32 * i;
        bulk_cp(Wd + row * FC1_ROW, w1 + (size_t)row * K_FC + kglob, 256, mbar);
    }
    bulk_cp(Gd + t * FC1_ROW, g + (size_t)t * K_FC + kglob, 256, mbar);
}

__global__ void __launch_bounds__(128, 2) fc1_kernel(const float *__restrict__ w1)
{
    extern __shared__ float sm[];
    float *Wb[2] = {sm, sm + FC1_W_FLOATS};
    float *Gb[2] = {sm + 2 * FC1_W_FLOATS, sm + 2 * FC1_W_FLOATS + FC1_G_FLOATS};
    __shared__ __align__(8) uint64_t mbar_s[2];
    uint32_t mb0 = s2u(&mbar_s[0]), mb1 = s2u(&mbar_s[1]);

    const float *g = d_g_buf;
    int t = threadIdx.x, bi = blockIdx.x;
    int s = t >> 6;                 // k-half
    int r = t & 63;
    int jg = r & 15, bg = r >> 4;   // j = jg + 16*jj (8), b = bg + 4*bb (8)

    int kstart, nst;
    if (bi < 248) { kstart = bi * 896; nst = 14; }
    else          { kstart = 222208 + (bi - 248) * 832; nst = 13; }

    if (t == 0) { mbar_init(mb0, 32); mbar_init(mb1, 32); }
    __syncthreads();

    if (t < 32) fc1_issue_stage(Wb[0], Gb[0], mb0, w1, g, kstart, t);

    float2 acc[8][8];
#pragma unroll
    for (int jj = 0; jj < 8; jj++)
#pragma unroll
        for (int bb = 0; bb < 8; bb++) acc[jj][bb] = make_float2(0.f, 0.f);

    for (int st = 0; st < nst; st++) {
        int slot = st & 1;
        if (st + 1 < nst && t < 32)
            fc1_issue_stage(Wb[slot ^ 1], Gb[slot ^ 1], slot ? mb0 : mb1,
                            w1, g, kstart + (st + 1) * 64, t);

        mbar_wait(slot ? mb1 : mb0, (st >> 1) & 1);

        const float *W = Wb[slot];
        const float *G = Gb[slot];
#pragma unroll
        for (int uu = 0; uu < 8; uu++) {
            int kq = 2 * uu + s;  // float4 index within stage (this k-half)
            float4 g4[8];
#pragma unroll
            for (int bb = 0; bb < 8; bb++)
                g4[bb] = *reinterpret_cast<const float4 *>(
                    G + (bg + 4 * bb) * FC1_ROW + kq * 4);
#pragma unroll
            for (int jj = 0; jj < 8; jj++) {
                float4 w4 = *reinterpret_cast<const float4 *>(
                    W + (jg + 16 * jj) * FC1_ROW + kq * 4);
                float2 wl = make_float2(w4.x, w4.y);
                float2 wh = make_float2(w4.z, w4.w);
#pragma unroll
                for (int bb = 0; bb < 8; bb++) {
                    fma2(acc[jj][bb], make_float2(g4[bb].x, g4[bb].y), wl);
                    fma2(acc[jj][bb], make_float2(g4[bb].z, g4[bb].w), wh);
                }
            }
        }
        __syncthreads();
    }

    float *pp = d_part_buf + ((size_t)bi * 2 + s) * 4096;
#pragma unroll
    for (int bb = 0; bb < 8; bb++)
#pragma unroll
        for (int jj = 0; jj < 8; jj++)
            pp[(bg + 4 * bb) * 128 + jg + 16 * jj] = acc[jj][bb].x + acc[jj][bb].y;
}

// ---------------------------------------------------------------------------
// Kernel 4a: reduce 592 partial sets -> relu(f1 + b1).  grid (32 b, 4 jq)
// ---------------------------------------------------------------------------
__global__ void __launch_bounds__(1024) fc1_reduce_kernel(const float *__restrict__ f1b)
{
    __shared__ float red[32][33];
    int t = threadIdx.x, b = blockIdx.x, jq = blockIdx.y;
    int jl = t & 31, sg = t >> 5;
    int j = jq * 32 + jl;

    const float *pp = d_part_buf + b * 128 + j;
    float ssum = 0.f;
    for (int i = sg; i < 592; i += 32) ssum += pp[(size_t)i * 4096];
    red[sg][jl] = ssum;
    __syncthreads();

    if (t < 32) {
        float v = 0.f;
#pragma unroll
        for (int u = 0; u < 32; u++) v += red[u][t];
        int jo = jq * 32 + t;
        d_f1_buf[b * 128 + jo] = fmaxf(v + f1b[jo], 0.f);
    }
}

// ---------------------------------------------------------------------------
// Kernel 4b: FC2 (101 x 128) + bias.  grid 32 (one block per batch)
// ---------------------------------------------------------------------------
__global__ void __launch_bounds__(128) fc2_kernel(
    const float *__restrict__ w2, const float *__restrict__ b2,
    float *__restrict__ out)
{
    __shared__ float f1s[128];
    int t = threadIdx.x, b = blockIdx.x;
    f1s[t] = d_f1_buf[b * 128 + t];
    __syncthreads();

    if (t < 101) {
        float acc = b2[t];
        const float *wr = w2 + t * 128;
#pragma unroll 8
        for (int jj = 0; jj < 128; jj++) acc = fmaf(f1s[jj], __ldg(&wr[jj]), acc);
        out[b * 101 + t] = acc;
    }
}

// ---------------------------------------------------------------------------
extern "C" void kernel_launch(void *const *d_in, const int *in_sizes, int n_in,
                              void *d_out, int out_size)
{
    (void)in_sizes; (void)n_in; (void)out_size;
    const float *x  = (const float *)d_in[0];
    const float *cw = (const float *)d_in[1];
    const float *cb = (const float *)d_in[2];
    const float *gw = (const float *)d_in[3];
    const float *gb = (const float *)d_in[4];
    const float *w1 = (const float *)d_in[5];
    const float *b1 = (const float *)d_in[6];
    const float *w2 = (const float *)d_in[7];
    const float *b2 = (const float *)d_in[8];
    float *out = (float *)d_out;

    const int gcn_smem = (512 * 36 + 2048 + 64) * 4;               // 82176 B
    const int fc1_smem = (2 * FC1_W_FLOATS + 2 * FC1_G_FLOATS) * 4; // 87040 B
    cudaFuncSetAttribute(gcn_kernel, cudaFuncAttributeMaxDynamicSharedMemorySize, gcn_smem);
    cudaFuncSetAttribute(fc1_kernel, cudaFuncAttributeMaxDynamicSharedMemorySize, fc1_smem);

    conv_pool_kernel<<<dim3(16, 32), 256>>>(x, cw, cb);   // launch 1
    gcn_kernel<<<dim3(8, 32), 256, gcn_smem>>>(gw, gb);   // launch 2
    nop_kernel<<<1, 32>>>();                              // launch 3 (profiling align)
    fc1_kernel<<<296, 128, fc1_smem>>>(w1);               // launch 4 <- ncu target
    fc1_reduce_kernel<<<dim3(32, 4), 1024>>>(b1);         // launch 5
    fc2_kernel<<<32, 128>>>(w2, b2, out);                 // launch 6
}

// round 5
// speedup vs baseline: 1.0381x; 1.0168x over previous
#include <cuda_runtime.h>
#include <cstdint>

// ---------------------------------------------------------------------------
// PartBasedGraphCNN: conv3x3(3->32)+relu+pool2 -> grid-GCN(32->64) -> FC1 -> FC2
// fp32, packed f32x2 FMA. FC1: cp.async.bulk staging, 4j x 8b tile, 256 thr,
// no register spills (R4 had regs=255 -> local-memory spill catastrophe).
// ---------------------------------------------------------------------------

#define K_FC 262144  // 4096 nodes * 64 feats

__device__ float d_pool_buf[32 * 32 * 64 * 64];     // [B][32][64][64]  16.8 MB
__device__ float d_g_buf[32u * 4096u * 64u];        // [B][N][64]       33.6 MB
__device__ float d_part_buf[592 * 32 * 128];        // [set][B][128]     9.7 MB
__device__ float d_f1_buf[32 * 128];                // [B][128]

__device__ __forceinline__ void fma2(float2 &d, const float2 a, const float2 b) {
    asm("fma.rn.f32x2 %0, %1, %2, %0;"
        : "+l"(*reinterpret_cast<unsigned long long *>(&d))
        : "l"(*reinterpret_cast<const unsigned long long *>(&a)),
          "l"(*reinterpret_cast<const unsigned long long *>(&b)));
}

__device__ __forceinline__ uint32_t s2u(const void *p) {
    return (uint32_t)__cvta_generic_to_shared(p);
}

__device__ __forceinline__ void bulk_cp(void *dst_smem, const void *src_gmem,
                                        uint32_t bytes, uint32_t mbar) {
    asm volatile(
        "cp.async.bulk.shared::cta.global.mbarrier::complete_tx::bytes "
        "[%0], [%1], %2, [%3];"
        :: "r"(s2u(dst_smem)), "l"(src_gmem), "r"(bytes), "r"(mbar) : "memory");
}

__device__ __forceinline__ void mbar_init(uint32_t mbar, uint32_t count) {
    asm volatile("mbarrier.init.shared::cta.b64 [%0], %1;" :: "r"(mbar), "r"(count));
}

__device__ __forceinline__ void mbar_expect_tx(uint32_t mbar, uint32_t bytes) {
    asm volatile("mbarrier.arrive.expect_tx.shared::cta.b64 _, [%0], %1;"
                 :: "r"(mbar), "r"(bytes) : "memory");
}

__device__ __forceinline__ void mbar_wait(uint32_t mbar, uint32_t parity) {
    asm volatile(
        "{\n\t"
        ".reg .pred P;\n\t"
        "WAIT_%=:\n\t"
        "mbarrier.try_wait.parity.acquire.cta.shared::cta.b64 P, [%0], %1, 0x989680;\n\t"
        "@P bra.uni DONE_%=;\n\t"
        "bra.uni WAIT_%=;\n\t"
        "DONE_%=:\n\t"
        "}"
        :: "r"(mbar), "r"(parity) : "memory");
}

// ---------------------------------------------------------------------------
// Kernel 1: conv 3x3 SAME + bias + relu + maxpool 2x2  (unchanged)
// ---------------------------------------------------------------------------
__global__ void __launch_bounds__(256) conv_pool_kernel(
    const float *__restrict__ x, const float *__restrict__ cw,
    const float *__restrict__ cb)
{
    __shared__ float sin_[3][34][34];
    __shared__ float wp[27 * 32];
    __shared__ float bb[32];

    int t = threadIdx.x;
    int b = blockIdx.y;
    int tpy = (blockIdx.x >> 2) * 16, tpx = (blockIdx.x & 3) * 16;

    for (int i = t; i < 864; i += 256) {
        int co = i / 27, rem = i % 27;
        wp[rem * 32 + co] = cw[i];
    }
    if (t < 32) bb[t] = cb[t];

    int oy = 2 * tpy - 1, ox = 2 * tpx - 1;
    for (int i = t; i < 3 * 34 * 34; i += 256) {
        int ci = i / 1156, rem = i % 1156, iy = rem / 34, ix = rem % 34;
        int gy = oy + iy, gx = ox + ix;
        float v = 0.f;
        if (gy >= 0 && gy < 128 && gx >= 0 && gx < 128)
            v = x[((b * 3 + ci) * 128 + gy) * 128 + gx];
        sin_[ci][iy][ix] = v;
    }
    __syncthreads();

    int py = t >> 4, px = t & 15;
    float in[3][4][4];
#pragma unroll
    for (int ci = 0; ci < 3; ci++)
#pragma unroll
        for (int r = 0; r < 4; r++)
#pragma unroll
            for (int c = 0; c < 4; c++)
                in[ci][r][c] = sin_[ci][2 * py + r][2 * px + c];

    const float2 *wp2 = reinterpret_cast<const float2 *>(wp);
    int gy = tpy + py, gx = tpx + px;
    float *outb = d_pool_buf + (size_t)b * 131072;

#pragma unroll
    for (int g = 0; g < 4; g++) {
        float2 acc[2][2][4];
#pragma unroll
        for (int dy = 0; dy < 2; dy++)
#pragma unroll
            for (int dx = 0; dx < 2; dx++)
#pragma unroll
                for (int p = 0; p < 4; p++) acc[dy][dx][p] = make_float2(0.f, 0.f);

#pragma unroll
        for (int ci = 0; ci < 3; ci++)
#pragma unroll
            for (int ky = 0; ky < 3; ky++)
#pragma unroll
                for (int kx = 0; kx < 3; kx++) {
                    int tap = ci * 9 + ky * 3 + kx;
                    float2 w0 = wp2[tap * 16 + g * 4 + 0];
                    float2 w1 = wp2[tap * 16 + g * 4 + 1];
                    float2 w2 = wp2[tap * 16 + g * 4 + 2];
                    float2 w3 = wp2[tap * 16 + g * 4 + 3];
#pragma unroll
                    for (int dy = 0; dy < 2; dy++)
#pragma unroll
                        for (int dx = 0; dx < 2; dx++) {
                            float iv = in[ci][dy + ky][dx + kx];
                            float2 iv2 = make_float2(iv, iv);
                            fma2(acc[dy][dx][0], iv2, w0);
                            fma2(acc[dy][dx][1], iv2, w1);
                            fma2(acc[dy][dx][2], iv2, w2);
                            fma2(acc[dy][dx][3], iv2, w3);
                        }
                }
#pragma unroll
        for (int p = 0; p < 4; p++) {
            int co = g * 8 + p * 2;
            float mx = fmaxf(fmaxf(acc[0][0][p].x, acc[0][1][p].x),
                             fmaxf(acc[1][0][p].x, acc[1][1][p].x));
            float my = fmaxf(fmaxf(acc[0][0][p].y, acc[0][1][p].y),
                             fmaxf(acc[1][0][p].y, acc[1][1][p].y));
            mx = fmaxf(mx + bb[co], 0.f);
            my = fmaxf(my + bb[co + 1], 0.f);
            outb[(co * 64 + gy) * 64 + gx] = mx;
            outb[((co + 1) * 64 + gy) * 64 + gx] = my;
        }
    }
}

// ---------------------------------------------------------------------------
// Kernel 2: GCN (stencil on 32-dim feats, then x32->64 GEMM)  (unchanged)
// ---------------------------------------------------------------------------
__device__ __forceinline__ float dinvf(int r, int c) {
    int deg = 1 + (r > 0) + (r < 63) + (c > 0) + (c < 63);
    return rsqrtf((float)deg);
}

__global__ void __launch_bounds__(256) gcn_kernel(
    const float *__restrict__ gw, const float *__restrict__ gb)
{
    extern __shared__ float sm[];
    float *aggx = sm;            // [512][36]
    float *wg = sm + 512 * 36;   // [32][64]
    float *bg = wg + 2048;       // [64]

    int t = threadIdx.x, b = blockIdx.y;
    int node0 = blockIdx.x * 512;

    for (int i = t; i < 2048; i += 256) wg[i] = gw[i];
    if (t < 64) bg[t] = gb[t];

    const float *nf = d_pool_buf + (size_t)b * 131072;
    int q = t & 7, ns = t >> 3;
#pragma unroll 4
    for (int i = 0; i < 16; i++) {
        int nl = ns + 32 * i;
        int n = node0 + nl;
        int r = n >> 6, c = n & 63;
        float dn = dinvf(r, c);
        const float4 *base = reinterpret_cast<const float4 *>(nf) + n * 8 + q;
        float4 v = __ldg(base);
        float4 a;
        a.x = dn * v.x; a.y = dn * v.y; a.z = dn * v.z; a.w = dn * v.w;
        if (r > 0) {
            float s = dinvf(r - 1, c); float4 u = __ldg(base - 512);
            a.x += s * u.x; a.y += s * u.y; a.z += s * u.z; a.w += s * u.w;
        }
        if (r < 63) {
            float s = dinvf(r + 1, c); float4 u = __ldg(base + 512);
            a.x += s * u.x; a.y += s * u.y; a.z += s * u.z; a.w += s * u.w;
        }
        if (c > 0) {
            float s = dinvf(r, c - 1); float4 u = __ldg(base - 8);
            a.x += s * u.x; a.y += s * u.y; a.z += s * u.z; a.w += s * u.w;
        }
        if (c < 63) {
            float s = dinvf(r, c + 1); float4 u = __ldg(base + 8);
            a.x += s * u.x; a.y += s * u.y; a.z += s * u.z; a.w += s * u.w;
        }
        a.x *= dn; a.y *= dn; a.z *= dn; a.w *= dn;
        *reinterpret_cast<float4 *>(&aggx[nl * 36 + q * 4]) = a;
    }
    __syncthreads();

    int ot = t & 7, ng = t >> 3;
    const float4 *wg4 = reinterpret_cast<const float4 *>(wg);
    float *gout = d_g_buf + (size_t)b * 262144;
#pragma unroll
    for (int it = 0; it < 2; it++) {
        int nb = (it * 32 + ng) * 8;
        float2 acc[8][4];
#pragma unroll
        for (int i = 0; i < 8; i++)
#pragma unroll
            for (int p = 0; p < 4; p++) acc[i][p] = make_float2(0.f, 0.f);

#pragma unroll 4
        for (int f = 0; f < 32; f++) {
            float4 wA = wg4[f * 16 + ot * 2];
            float4 wB = wg4[f * 16 + ot * 2 + 1];
            float2 p0 = make_float2(wA.x, wA.y), p1 = make_float2(wA.z, wA.w);
            float2 p2 = make_float2(wB.x, wB.y), p3 = make_float2(wB.z, wB.w);
#pragma unroll
            for (int i = 0; i < 8; i++) {
                float av = aggx[(nb + i) * 36 + f];
                float2 ad = make_float2(av, av);
                fma2(acc[i][0], ad, p0);
                fma2(acc[i][1], ad, p1);
                fma2(acc[i][2], ad, p2);
                fma2(acc[i][3], ad, p3);
            }
        }
#pragma unroll
        for (int i = 0; i < 8; i++) {
            float2 *op = reinterpret_cast<float2 *>(
                gout + (size_t)(node0 + nb + i) * 64 + ot * 8);
#pragma unroll
            for (int p = 0; p < 4; p++) {
                float2 v;
                v.x = fmaxf(acc[i][p].x + bg[ot * 8 + 2 * p], 0.f);
                v.y = fmaxf(acc[i][p].y + bg[ot * 8 + 2 * p + 1], 0.f);
                op[p] = v;
            }
        }
    }
}

// ---------------------------------------------------------------------------
// Dummy kernel: keeps fc1_kernel as the 4th launch (ncu profiles launch #4).
// ---------------------------------------------------------------------------
__global__ void nop_kernel() {}

// ---------------------------------------------------------------------------
// Kernel 3: FC1. 296 blocks x 256 threads (2/SM), double-buffered
// cp.async.bulk stages of 64 k. 2-way k-split (128 threads per half).
// Thread tile 4j x 8b: j = lane + 32*jj (W rows lane-varying, stride-68
// rows -> conflict-free LDS.128), b = warp*8 + bb (G loads warp-broadcast).
// acc = 32 float2 = 64 regs -> no spills.
// ---------------------------------------------------------------------------
#define FC1_ROW 68               // floats per padded row (272 B)
#define FC1_W_FLOATS (128 * FC1_ROW)
#define FC1_G_FLOATS (32 * FC1_ROW)

__device__ __forceinline__ void fc1_issue_stage(
    float *Wd, float *Gd, uint32_t mbar,
    const float *__restrict__ w1, const float *__restrict__ g, int kglob, int t)
{
    // 32 issuing threads; each: 4 W rows + 1 G row = 5 x 256B = 1280 B
    mbar_expect_tx(mbar, 1280);
#pragma unroll
    for (int i = 0; i < 4; i++) {
        int row = t + 32 * i;
        bulk_cp(Wd + row * FC1_ROW, w1 + (size_t)row * K_FC + kglob, 256, mbar);
    }
    bulk_cp(Gd + t * FC1_ROW, g + (size_t)t * K_FC + kglob, 256, mbar);
}

__global__ void __launch_bounds__(256, 2) fc1_kernel(const float *__restrict__ w1)
{
    extern __shared__ float sm[];
    float *Wb[2] = {sm, sm + FC1_W_FLOATS};
    float *Gb[2] = {sm + 2 * FC1_W_FLOATS, sm + 2 * FC1_W_FLOATS + FC1_G_FLOATS};
    __shared__ __align__(8) uint64_t mbar_s[2];
    uint32_t mb0 = s2u(&mbar_s[0]), mb1 = s2u(&mbar_s[1]);

    const float *g = d_g_buf;
    int t = threadIdx.x, bi = blockIdx.x;
    int s = t >> 7;                 // k-half
    int r = t & 127;
    int lane = r & 31, w = r >> 5;  // j = lane + 32*jj, b = w*8 + bb

    int kstart, nst;
    if (bi < 248) { kstart = bi * 896; nst = 14; }
    else          { kstart = 222208 + (bi - 248) * 832; nst = 13; }

    if (t == 0) { mbar_init(mb0, 32); mbar_init(mb1, 32); }
    __syncthreads();

    if (t < 32) fc1_issue_stage(Wb[0], Gb[0], mb0, w1, g, kstart, t);

    float2 acc[4][8];
#pragma unroll
    for (int jj = 0; jj < 4; jj++)
#pragma unroll
        for (int bb = 0; bb < 8; bb++) acc[jj][bb] = make_float2(0.f, 0.f);

    for (int st = 0; st < nst; st++) {
        int slot = st & 1;
        if (st + 1 < nst && t < 32)
            fc1_issue_stage(Wb[slot ^ 1], Gb[slot ^ 1], slot ? mb0 : mb1,
                            w1, g, kstart + (st + 1) * 64, t);

        mbar_wait(slot ? mb1 : mb0, (st >> 1) & 1);

        const float *W = Wb[slot];
        const float *G = Gb[slot];
#pragma unroll
        for (int uu = 0; uu < 8; uu++) {
            int kq = 2 * uu + s;  // float4 index within stage (this k-half)
            float4 w4[4];
#pragma unroll
            for (int jj = 0; jj < 4; jj++)
                w4[jj] = *reinterpret_cast<const float4 *>(
                    W + (lane + 32 * jj) * FC1_ROW + kq * 4);
#pragma unroll
            for (int bb = 0; bb < 8; bb++) {
                float4 g4 = *reinterpret_cast<const float4 *>(
                    G + (w * 8 + bb) * FC1_ROW + kq * 4);
                float2 gl = make_float2(g4.x, g4.y);
                float2 gh = make_float2(g4.z, g4.w);
#pragma unroll
                for (int jj = 0; jj < 4; jj++) {
                    fma2(acc[jj][bb], gl, make_float2(w4[jj].x, w4[jj].y));
                    fma2(acc[jj][bb], gh, make_float2(w4[jj].z, w4[jj].w));
                }
            }
        }
        __syncthreads();
    }

    float *pp = d_part_buf + ((size_t)bi * 2 + s) * 4096;
#pragma unroll
    for (int bb = 0; bb < 8; bb++)
#pragma unroll
        for (int jj = 0; jj < 4; jj++)
            pp[(w * 8 + bb) * 128 + lane + 32 * jj] = acc[jj][bb].x + acc[jj][bb].y;
}

// ---------------------------------------------------------------------------
// Kernel 4a: reduce 592 partial sets -> relu(f1 + b1).  grid (32 b, 4 jq)
// ---------------------------------------------------------------------------
__global__ void __launch_bounds__(1024) fc1_reduce_kernel(const float *__restrict__ f1b)
{
    __shared__ float red[32][33];
    int t = threadIdx.x, b = blockIdx.x, jq = blockIdx.y;
    int jl = t & 31, sg = t >> 5;
    int j = jq * 32 + jl;

    const float *pp = d_part_buf + b * 128 + j;
    float ssum = 0.f;
    for (int i = sg; i < 592; i += 32) ssum += pp[(size_t)i * 4096];
    red[sg][jl] = ssum;
    __syncthreads();

    if (t < 32) {
        float v = 0.f;
#pragma unroll
        for (int u = 0; u < 32; u++) v += red[u][t];
        int jo = jq * 32 + t;
        d_f1_buf[b * 128 + jo] = fmaxf(v + f1b[jo], 0.f);
    }
}

// ---------------------------------------------------------------------------
// Kernel 4b: FC2 (101 x 128) + bias.  grid 32 (one block per batch)
// ---------------------------------------------------------------------------
__global__ void __launch_bounds__(128) fc2_kernel(
    const float *__restrict__ w2, const float *__restrict__ b2,
    float *__restrict__ out)
{
    __shared__ float f1s[128];
    int t = threadIdx.x, b = blockIdx.x;
    f1s[t] = d_f1_buf[b * 128 + t];
    __syncthreads();

    if (t < 101) {
        float acc = b2[t];
        const float *wr = w2 + t * 128;
#pragma unroll 8
        for (int jj = 0; jj < 128; jj++) acc = fmaf(f1s[jj], __ldg(&wr[jj]), acc);
        out[b * 101 + t] = acc;
    }
}

// ---------------------------------------------------------------------------
extern "C" void kernel_launch(void *const *d_in, const int *in_sizes, int n_in,
                              void *d_out, int out_size)
{
    (void)in_sizes; (void)n_in; (void)out_size;
    const float *x  = (const float *)d_in[0];
    const float *cw = (const float *)d_in[1];
    const float *cb = (const float *)d_in[2];
    const float *gw = (const float *)d_in[3];
    const float *gb = (const float *)d_in[4];
    const float *w1 = (const float *)d_in[5];
    const float *b1 = (const float *)d_in[6];
    const float *w2 = (const float *)d_in[7];
    const float *b2 = (const float *)d_in[8];
    float *out = (float *)d_out;

    const int gcn_smem = (512 * 36 + 2048 + 64) * 4;               // 82176 B
    const int fc1_smem = (2 * FC1_W_FLOATS + 2 * FC1_G_FLOATS) * 4; // 87040 B
    cudaFuncSetAttribute(gcn_kernel, cudaFuncAttributeMaxDynamicSharedMemorySize, gcn_smem);
    cudaFuncSetAttribute(fc1_kernel, cudaFuncAttributeMaxDynamicSharedMemorySize, fc1_smem);

    conv_pool_kernel<<<dim3(16, 32), 256>>>(x, cw, cb);   // launch 1
    gcn_kernel<<<dim3(8, 32), 256, gcn_smem>>>(gw, gb);   // launch 2
    nop_kernel<<<1, 32>>>();                              // launch 3 (profiling align)
    fc1_kernel<<<296, 256, fc1_smem>>>(w1);               // launch 4 <- ncu target
    fc1_reduce_kernel<<<dim3(32, 4), 1024>>>(b1);         // launch 5
    fc2_kernel<<<32, 128>>>(w2, b2, out);                 // launch 6
}

// round 7
// speedup vs baseline: 1.1254x; 1.0841x over previous
#include <cuda_runtime.h>
#include <cstdint>

// ---------------------------------------------------------------------------
// PartBasedGraphCNN: conv3x3(3->32)+relu+pool2 -> grid-GCN(32->64) -> FC1 -> FC2
// FC1 = bf16-split HMMA GEMM (mma.sync m16n8k16, base-PTX legal on compute_103):
// D[128x32] = W*G^T, split-K over 296 CTAs, cp.async.bulk fp32 staging,
// register-side fp32->bf16 hi/lo conversion (Wh*Gh + Wh*Gl + Wl*Gh).
// ---------------------------------------------------------------------------

#define K_FC 262144  // 4096 nodes * 64 feats

__device__ float d_pool_buf[32 * 32 * 64 * 64];     // [B][32][64][64]  16.8 MB
__device__ float d_g_buf[32u * 4096u * 64u];        // [B][N][64]       33.6 MB
__device__ float d_part_buf[296 * 32 * 128];        // [set][B][128]     4.9 MB
__device__ float d_f1_buf[32 * 128];                // [B][128]

__device__ __forceinline__ void fma2(float2 &d, const float2 a, const float2 b) {
    asm("fma.rn.f32x2 %0, %1, %2, %0;"
        : "+l"(*reinterpret_cast<unsigned long long *>(&d))
        : "l"(*reinterpret_cast<const unsigned long long *>(&a)),
          "l"(*reinterpret_cast<const unsigned long long *>(&b)));
}

__device__ __forceinline__ uint32_t s2u(const void *p) {
    return (uint32_t)__cvta_generic_to_shared(p);
}

__device__ __forceinline__ void bulk_cp(uint32_t dst_smem, const void *src_gmem,
                                        uint32_t bytes, uint32_t mbar) {
    asm volatile(
        "cp.async.bulk.shared::cta.global.mbarrier::complete_tx::bytes "
        "[%0], [%1], %2, [%3];"
        :: "r"(dst_smem), "l"(src_gmem), "r"(bytes), "r"(mbar) : "memory");
}

__device__ __forceinline__ void mbar_init(uint32_t mbar, uint32_t count) {
    asm volatile("mbarrier.init.shared::cta.b64 [%0], %1;" :: "r"(mbar), "r"(count));
}

__device__ __forceinline__ void mbar_expect_tx(uint32_t mbar, uint32_t bytes) {
    asm volatile("mbarrier.arrive.expect_tx.shared::cta.b64 _, [%0], %1;"
                 :: "r"(mbar), "r"(bytes) : "memory");
}

__device__ __forceinline__ void mbar_wait(uint32_t mbar, uint32_t parity) {
    asm volatile(
        "{\n\t"
        ".reg .pred P;\n\t"
        "WAIT_%=:\n\t"
        "mbarrier.try_wait.parity.acquire.cta.shared::cta.b64 P, [%0], %1, 0x989680;\n\t"
        "@P bra.uni DONE_%=;\n\t"
        "bra.uni WAIT_%=;\n\t"
        "DONE_%=:\n\t"
        "}"
        :: "r"(mbar), "r"(parity) : "memory");
}

// fp32 pair -> bf16x2 hi + bf16x2 lo (residual). lo half of reg = even elem.
__device__ __forceinline__ void cvt_hilo(float2 f, uint32_t &hi, uint32_t &lo) {
    asm("cvt.rn.bf16x2.f32 %0, %1, %2;" : "=r"(hi) : "f"(f.y), "f"(f.x));
    float rx = f.x - __uint_as_float(hi << 16);
    float ry = f.y - __uint_as_float(hi & 0xFFFF0000u);
    asm("cvt.rn.bf16x2.f32 %0, %1, %2;" : "=r"(lo) : "f"(ry), "f"(rx));
}

// m16n8k16 row.col bf16 HMMA, D=C in-place
__device__ __forceinline__ void mma_bf16(float *d, const uint32_t *a,
                                         const uint32_t *b) {
    asm volatile(
        "mma.sync.aligned.m16n8k16.row.col.f32.bf16.bf16.f32 "
        "{%0,%1,%2,%3}, {%4,%5,%6,%7}, {%8,%9}, {%0,%1,%2,%3};"
        : "+f"(d[0]), "+f"(d[1]), "+f"(d[2]), "+f"(d[3])
        : "r"(a[0]), "r"(a[1]), "r"(a[2]), "r"(a[3]), "r"(b[0]), "r"(b[1]));
}

// ---------------------------------------------------------------------------
// Kernel 1: conv 3x3 SAME + bias + relu + maxpool 2x2  (unchanged)
// ---------------------------------------------------------------------------
__global__ void __launch_bounds__(256) conv_pool_kernel(
    const float *__restrict__ x, const float *__restrict__ cw,
    const float *__restrict__ cb)
{
    __shared__ float sin_[3][34][34];
    __shared__ float wp[27 * 32];
    __shared__ float bb[32];

    int t = threadIdx.x;
    int b = blockIdx.y;
    int tpy = (blockIdx.x >> 2) * 16, tpx = (blockIdx.x & 3) * 16;

    for (int i = t; i < 864; i += 256) {
        int co = i / 27, rem = i % 27;
        wp[rem * 32 + co] = cw[i];
    }
    if (t < 32) bb[t] = cb[t];

    int oy = 2 * tpy - 1, ox = 2 * tpx - 1;
    for (int i = t; i < 3 * 34 * 34; i += 256) {
        int ci = i / 1156, rem = i % 1156, iy = rem / 34, ix = rem % 34;
        int gy = oy + iy, gx = ox + ix;
        float v = 0.f;
        if (gy >= 0 && gy < 128 && gx >= 0 && gx < 128)
            v = x[((b * 3 + ci) * 128 + gy) * 128 + gx];
        sin_[ci][iy][ix] = v;
    }
    __syncthreads();

    int py = t >> 4, px = t & 15;
    float in[3][4][4];
#pragma unroll
    for (int ci = 0; ci < 3; ci++)
#pragma unroll
        for (int r = 0; r < 4; r++)
#pragma unroll
            for (int c = 0; c < 4; c++)
                in[ci][r][c] = sin_[ci][2 * py + r][2 * px + c];

    const float2 *wp2 = reinterpret_cast<const float2 *>(wp);
    int gy = tpy + py, gx = tpx + px;
    float *outb = d_pool_buf + (size_t)b * 131072;

#pragma unroll
    for (int g = 0; g < 4; g++) {
        float2 acc[2][2][4];
#pragma unroll
        for (int dy = 0; dy < 2; dy++)
#pragma unroll
            for (int dx = 0; dx < 2; dx++)
#pragma unroll
                for (int p = 0; p < 4; p++) acc[dy][dx][p] = make_float2(0.f, 0.f);

#pragma unroll
        for (int ci = 0; ci < 3; ci++)
#pragma unroll
            for (int ky = 0; ky < 3; ky++)
#pragma unroll
                for (int kx = 0; kx < 3; kx++) {
                    int tap = ci * 9 + ky * 3 + kx;
                    float2 w0 = wp2[tap * 16 + g * 4 + 0];
                    float2 w1 = wp2[tap * 16 + g * 4 + 1];
                    float2 w2 = wp2[tap * 16 + g * 4 + 2];
                    float2 w3 = wp2[tap * 16 + g * 4 + 3];
#pragma unroll
                    for (int dy = 0; dy < 2; dy++)
#pragma unroll
                        for (int dx = 0; dx < 2; dx++) {
                            float iv = in[ci][dy + ky][dx + kx];
                            float2 iv2 = make_float2(iv, iv);
                            fma2(acc[dy][dx][0], iv2, w0);
                            fma2(acc[dy][dx][1], iv2, w1);
                            fma2(acc[dy][dx][2], iv2, w2);
                            fma2(acc[dy][dx][3], iv2, w3);
                        }
                }
#pragma unroll
        for (int p = 0; p < 4; p++) {
            int co = g * 8 + p * 2;
            float mx = fmaxf(fmaxf(acc[0][0][p].x, acc[0][1][p].x),
                             fmaxf(acc[1][0][p].x, acc[1][1][p].x));
            float my = fmaxf(fmaxf(acc[0][0][p].y, acc[0][1][p].y),
                             fmaxf(acc[1][0][p].y, acc[1][1][p].y));
            mx = fmaxf(mx + bb[co], 0.f);
            my = fmaxf(my + bb[co + 1], 0.f);
            outb[(co * 64 + gy) * 64 + gx] = mx;
            outb[((co + 1) * 64 + gy) * 64 + gx] = my;
        }
    }
}

// ---------------------------------------------------------------------------
// Kernel 2: GCN (stencil on 32-dim feats, then x32->64 GEMM)  (unchanged)
// ---------------------------------------------------------------------------
__device__ __forceinline__ float dinvf(int r, int c) {
    int deg = 1 + (r > 0) + (r < 63) + (c > 0) + (c < 63);
    return rsqrtf((float)deg);
}

__global__ void __launch_bounds__(256) gcn_kernel(
    const float *__restrict__ gw, const float *__restrict__ gb)
{
    extern __shared__ float sm[];
    float *aggx = sm;            // [512][36]
    float *wg = sm + 512 * 36;   // [32][64]
    float *bg = wg + 2048;       // [64]

    int t = threadIdx.x, b = blockIdx.y;
    int node0 = blockIdx.x * 512;

    for (int i = t; i < 2048; i += 256) wg[i] = gw[i];
    if (t < 64) bg[t] = gb[t];

    const float *nf = d_pool_buf + (size_t)b * 131072;
    int q = t & 7, ns = t >> 3;
#pragma unroll 4
    for (int i = 0; i < 16; i++) {
        int nl = ns + 32 * i;
        int n = node0 + nl;
        int r = n >> 6, c = n & 63;
        float dn = dinvf(r, c);
        const float4 *base = reinterpret_cast<const float4 *>(nf) + n * 8 + q;
        float4 v = __ldg(base);
        float4 a;
        a.x = dn * v.x; a.y = dn * v.y; a.z = dn * v.z; a.w = dn * v.w;
        if (r > 0) {
            float s = dinvf(r - 1, c); float4 u = __ldg(base - 512);
            a.x += s * u.x; a.y += s * u.y; a.z += s * u.z; a.w += s * u.w;
        }
        if (r < 63) {
            float s = dinvf(r + 1, c); float4 u = __ldg(base + 512);
            a.x += s * u.x; a.y += s * u.y; a.z += s * u.z; a.w += s * u.w;
        }
        if (c > 0) {
            float s = dinvf(r, c - 1); float4 u = __ldg(base - 8);
            a.x += s * u.x; a.y += s * u.y; a.z += s * u.z; a.w += s * u.w;
        }
        if (c < 63) {
            float s = dinvf(r, c + 1); float4 u = __ldg(base + 8);
            a.x += s * u.x; a.y += s * u.y; a.z += s * u.z; a.w += s * u.w;
        }
        a.x *= dn; a.y *= dn; a.z *= dn; a.w *= dn;
        *reinterpret_cast<float4 *>(&aggx[nl * 36 + q * 4]) = a;
    }
    __syncthreads();

    int ot = t & 7, ng = t >> 3;
    const float4 *wg4 = reinterpret_cast<const float4 *>(wg);
    float *gout = d_g_buf + (size_t)b * 262144;
#pragma unroll
    for (int it = 0; it < 2; it++) {
        int nb = (it * 32 + ng) * 8;
        float2 acc[8][4];
#pragma unroll
        for (int i = 0; i < 8; i++)
#pragma unroll
            for (int p = 0; p < 4; p++) acc[i][p] = make_float2(0.f, 0.f);

#pragma unroll 4
        for (int f = 0; f < 32; f++) {
            float4 wA = wg4[f * 16 + ot * 2];
            float4 wB = wg4[f * 16 + ot * 2 + 1];
            float2 p0 = make_float2(wA.x, wA.y), p1 = make_float2(wA.z, wA.w);
            float2 p2 = make_float2(wB.x, wB.y), p3 = make_float2(wB.z, wB.w);
#pragma unroll
            for (int i = 0; i < 8; i++) {
                float av = aggx[(nb + i) * 36 + f];
                float2 ad = make_float2(av, av);
                fma2(acc[i][0], ad, p0);
                fma2(acc[i][1], ad, p1);
                fma2(acc[i][2], ad, p2);
                fma2(acc[i][3], ad, p3);
            }
        }
#pragma unroll
        for (int i = 0; i < 8; i++) {
            float2 *op = reinterpret_cast<float2 *>(
                gout + (size_t)(node0 + nb + i) * 64 + ot * 8);
#pragma unroll
            for (int p = 0; p < 4; p++) {
                float2 v;
                v.x = fmaxf(acc[i][p].x + bg[ot * 8 + 2 * p], 0.f);
                v.y = fmaxf(acc[i][p].y + bg[ot * 8 + 2 * p + 1], 0.f);
                op[p] = v;
            }
        }
    }
}

// ---------------------------------------------------------------------------
// Dummy kernel: keeps fc1_kernel as the 4th launch (ncu profiles launch #4).
// ---------------------------------------------------------------------------
__global__ void nop_kernel() {}

// ---------------------------------------------------------------------------
// Kernel 3: FC1 HMMA GEMM.  296 CTAs (2/SM) x 288 threads.
// Warp 8 stages fp32 W[128x64]+G[32x64] chunks via cp.async.bulk (double buf);
// warps 0-7 each own D rows 16w..16w+15 x 32 cols: per k16 step load float2
// fragments from fp32 smem, convert to bf16 hi/lo in regs, 12 HMMA
// (AhBh + AhBl + AlBh over 4 n-tiles) into fp32 register accumulators.
// ---------------------------------------------------------------------------
#define FC1_ROW 68                    // floats per padded row (272 B)
#define FP_G    (128 * FC1_ROW)      // float offset of G rows in a stage buffer
#define SM_TMA0 0
#define SM_TMA1 8
#define SM_FP0  1024
#define SM_FP1  (SM_FP0 + 43520)     // (128+32)*68*4 = 43520 B per stage
#define FC1_SMEM (SM_FP1 + 43520)    // 88064 B

__device__ __forceinline__ void fc1_issue_tma(
    uint32_t fp_dst, uint32_t mbar, const float *__restrict__ w1,
    const float *__restrict__ g, int kglob, int lane)
{
    mbar_expect_tx(mbar, 1280);  // 5 x 256B per lane; 32 lanes -> 40960 total
#pragma unroll
    for (int i = 0; i < 4; i++) {
        int row = lane + 32 * i;
        bulk_cp(fp_dst + row * (FC1_ROW * 4), w1 + (size_t)row * K_FC + kglob,
                256, mbar);
    }
    bulk_cp(fp_dst + (FP_G + lane * FC1_ROW) * 4, g + (size_t)lane * K_FC + kglob,
            256, mbar);
}

__global__ void __launch_bounds__(288, 2) fc1_kernel(const float *__restrict__ w1)
{
    extern __shared__ float smf[];
    uint32_t sb = s2u(smf);
    int t = threadIdx.x, lane = t & 31, w = t >> 5;
    int bi = blockIdx.x;
    const float *g = d_g_buf;

    int kstart, nst;
    if (bi < 272) { kstart = bi * 896; nst = 14; }
    else          { kstart = 272 * 896 + (bi - 272) * 768; nst = 12; }

    if (t == 0) { mbar_init(sb + SM_TMA0, 32); mbar_init(sb + SM_TMA1, 32); }
    __syncthreads();

    if (w == 8) fc1_issue_tma(sb + SM_FP0, sb + SM_TMA0, w1, g, kstart, lane);

    // accumulators: 4 n-tiles x 4 regs
    float acc[4][4];
#pragma unroll
    for (int nt = 0; nt < 4; nt++)
#pragma unroll
        for (int p = 0; p < 4; p++) acc[nt][p] = 0.f;

    int q = lane >> 2, kc = (lane & 3) * 2;   // fragment coords
    int mbase = 16 * w;

    for (int st = 0; st < nst; st++) {
        int slot = st & 1;
        if (w == 8 && st + 1 < nst)
            fc1_issue_tma(sb + (slot ? SM_FP0 : SM_FP1),
                          sb + (slot ? SM_TMA0 : SM_TMA1),
                          w1, g, kstart + (st + 1) * 64, lane);

        mbar_wait(sb + (slot ? SM_TMA1 : SM_TMA0), (st >> 1) & 1);

        if (w < 8) {
            const float *Wfp = smf + (slot ? SM_FP1 : SM_FP0) / 4;
            const float *Gfp = Wfp + FP_G;
#pragma unroll
            for (int ks = 0; ks < 4; ks++) {
                int k0 = ks * 16;
                // A fragments (16x16 @ rows mbase..mbase+15)
                float2 fa0 = *reinterpret_cast<const float2 *>(
                    Wfp + (mbase + q) * FC1_ROW + k0 + kc);
                float2 fa1 = *reinterpret_cast<const float2 *>(
                    Wfp + (mbase + q + 8) * FC1_ROW + k0 + kc);
                float2 fa2 = *reinterpret_cast<const float2 *>(
                    Wfp + (mbase + q) * FC1_ROW + k0 + kc + 8);
                float2 fa3 = *reinterpret_cast<const float2 *>(
                    Wfp + (mbase + q + 8) * FC1_ROW + k0 + kc + 8);
                uint32_t Ah[4], Al[4];
                cvt_hilo(fa0, Ah[0], Al[0]);
                cvt_hilo(fa1, Ah[1], Al[1]);
                cvt_hilo(fa2, Ah[2], Al[2]);
                cvt_hilo(fa3, Ah[3], Al[3]);
#pragma unroll
                for (int nt = 0; nt < 4; nt++) {
                    int n = nt * 8 + q;
                    float2 fb0 = *reinterpret_cast<const float2 *>(
                        Gfp + n * FC1_ROW + k0 + kc);
                    float2 fb1 = *reinterpret_cast<const float2 *>(
                        Gfp + n * FC1_ROW + k0 + kc + 8);
                    uint32_t Bh[2], Bl[2];
                    cvt_hilo(fb0, Bh[0], Bl[0]);
                    cvt_hilo(fb1, Bh[1], Bl[1]);
                    mma_bf16(acc[nt], Ah, Bh);
                    mma_bf16(acc[nt], Ah, Bl);
                    mma_bf16(acc[nt], Al, Bh);
                }
            }
        }
        __syncthreads();
    }

    if (w < 8) {
        float *pp = d_part_buf + (size_t)bi * 4096;
        int cb = (lane & 3) * 2;
#pragma unroll
        for (int nt = 0; nt < 4; nt++) {
            int n0 = nt * 8 + cb;
            pp[(n0    ) * 128 + mbase + q    ] = acc[nt][0];
            pp[(n0 + 1) * 128 + mbase + q    ] = acc[nt][1];
            pp[(n0    ) * 128 + mbase + q + 8] = acc[nt][2];
            pp[(n0 + 1) * 128 + mbase + q + 8] = acc[nt][3];
        }
    }
}

// ---------------------------------------------------------------------------
// Kernel 4a: reduce 296 partial sets -> relu(f1 + b1).  grid (32 b, 4 jq)
// ---------------------------------------------------------------------------
__global__ void __launch_bounds__(1024) fc1_reduce_kernel(const float *__restrict__ f1b)
{
    __shared__ float red[32][33];
    int t = threadIdx.x, b = blockIdx.x, jq = blockIdx.y;
    int jl = t & 31, sg = t >> 5;
    int j = jq * 32 + jl;

    const float *pp = d_part_buf + b * 128 + j;
    float ssum = 0.f;
    for (int i = sg; i < 296; i += 32) ssum += pp[(size_t)i * 4096];
    red[sg][jl] = ssum;
    __syncthreads();

    if (t < 32) {
        float v = 0.f;
#pragma unroll
        for (int u = 0; u < 32; u++) v += red[u][t];
        int jo = jq * 32 + t;
        d_f1_buf[b * 128 + jo] = fmaxf(v + f1b[jo], 0.f);
    }
}

// ---------------------------------------------------------------------------
// Kernel 4b: FC2 (101 x 128) + bias.  grid 32 (one block per batch)
// ---------------------------------------------------------------------------
__global__ void __launch_bounds__(128) fc2_kernel(
    const float *__restrict__ w2, const float *__restrict__ b2,
    float *__restrict__ out)
{
    __shared__ float f1s[128];
    int t = threadIdx.x, b = blockIdx.x;
    f1s[t] = d_f1_buf[b * 128 + t];
    __syncthreads();

    if (t < 101) {
        float acc = b2[t];
        const float *wr = w2 + t * 128;
#pragma unroll 8
        for (int jj = 0; jj < 128; jj++) acc = fmaf(f1s[jj], __ldg(&wr[jj]), acc);
        out[b * 101 + t] = acc;
    }
}

// ---------------------------------------------------------------------------
extern "C" void kernel_launch(void *const *d_in, const int *in_sizes, int n_in,
                              void *d_out, int out_size)
{
    (void)in_sizes; (void)n_in; (void)out_size;
    const float *x  = (const float *)d_in[0];
    const float *cw = (const float *)d_in[1];
    const float *cb = (const float *)d_in[2];
    const float *gw = (const float *)d_in[3];
    const float *gb = (const float *)d_in[4];
    const float *w1 = (const float *)d_in[5];
    const float *b1 = (const float *)d_in[6];
    const float *w2 = (const float *)d_in[7];
    const float *b2 = (const float *)d_in[8];
    float *out = (float *)d_out;

    const int gcn_smem = (512 * 36 + 2048 + 64) * 4;  // 82176 B
    cudaFuncSetAttribute(gcn_kernel, cudaFuncAttributeMaxDynamicSharedMemorySize, gcn_smem);
    cudaFuncSetAttribute(fc1_kernel, cudaFuncAttributeMaxDynamicSharedMemorySize, FC1_SMEM);

    conv_pool_kernel<<<dim3(16, 32), 256>>>(x, cw, cb);   // launch 1
    gcn_kernel<<<dim3(8, 32), 256, gcn_smem>>>(gw, gb);   // launch 2
    nop_kernel<<<1, 32>>>();                              // launch 3 (profiling align)
    fc1_kernel<<<296, 288, FC1_SMEM>>>(w1);               // launch 4 <- ncu target
    fc1_reduce_kernel<<<dim3(32, 4), 1024>>>(b1);         // launch 5
    fc2_kernel<<<32, 128>>>(w2, b2, out);                 // launch 6
}

// round 8
// speedup vs baseline: 1.2566x; 1.1166x over previous
#include <cuda_runtime.h>
#include <cstdint>

// ---------------------------------------------------------------------------
// PartBasedGraphCNN: conv3x3(3->32)+relu+pool2 -> grid-GCN(32->64) -> FC1 -> FC2
// FC1 = bf16-split HMMA GEMM, streaming: W fragments via __ldg from gmem
// (no staging), G pre-converted to bf16 hi/lo by GCN and TMA-staged ONCE per
// CTA. Split-K over 512 CTAs (K=512 each), no per-stage barriers.
// ---------------------------------------------------------------------------

#define K_FC 262144  // 4096 nodes * 64 feats

__device__ float d_pool_buf[32 * 32 * 64 * 64];       // [B][32][64][64] 16.8 MB
__device__ uint16_t d_g_hi[32u * 262144u];            // [B][K] bf16 hi  16.8 MB
__device__ uint16_t d_g_lo[32u * 262144u];            // [B][K] bf16 lo  16.8 MB
__device__ float d_part_buf[512 * 32 * 128];          // [set][B][128]    8.4 MB
__device__ float d_f1_buf[32 * 128];                  // [B][128]

__device__ __forceinline__ void fma2(float2 &d, const float2 a, const float2 b) {
    asm("fma.rn.f32x2 %0, %1, %2, %0;"
        : "+l"(*reinterpret_cast<unsigned long long *>(&d))
        : "l"(*reinterpret_cast<const unsigned long long *>(&a)),
          "l"(*reinterpret_cast<const unsigned long long *>(&b)));
}

__device__ __forceinline__ uint32_t s2u(const void *p) {
    return (uint32_t)__cvta_generic_to_shared(p);
}

__device__ __forceinline__ void bulk_cp(uint32_t dst_smem, const void *src_gmem,
                                        uint32_t bytes, uint32_t mbar) {
    asm volatile(
        "cp.async.bulk.shared::cta.global.mbarrier::complete_tx::bytes "
        "[%0], [%1], %2, [%3];"
        :: "r"(dst_smem), "l"(src_gmem), "r"(bytes), "r"(mbar) : "memory");
}

__device__ __forceinline__ void mbar_init(uint32_t mbar, uint32_t count) {
    asm volatile("mbarrier.init.shared::cta.b64 [%0], %1;" :: "r"(mbar), "r"(count));
}

__device__ __forceinline__ void mbar_expect_tx(uint32_t mbar, uint32_t bytes) {
    asm volatile("mbarrier.arrive.expect_tx.shared::cta.b64 _, [%0], %1;"
                 :: "r"(mbar), "r"(bytes) : "memory");
}

__device__ __forceinline__ void mbar_wait(uint32_t mbar, uint32_t parity) {
    asm volatile(
        "{\n\t"
        ".reg .pred P;\n\t"
        "WAIT_%=:\n\t"
        "mbarrier.try_wait.parity.acquire.cta.shared::cta.b64 P, [%0], %1, 0x989680;\n\t"
        "@P bra.uni DONE_%=;\n\t"
        "bra.uni WAIT_%=;\n\t"
        "DONE_%=:\n\t"
        "}"
        :: "r"(mbar), "r"(parity) : "memory");
}

// fp32 pair -> bf16x2 hi + bf16x2 lo (residual). lo half of reg = even elem.
__device__ __forceinline__ void cvt_hilo(float2 f, uint32_t &hi, uint32_t &lo) {
    asm("cvt.rn.bf16x2.f32 %0, %1, %2;" : "=r"(hi) : "f"(f.y), "f"(f.x));
    float rx = f.x - __uint_as_float(hi << 16);
    float ry = f.y - __uint_as_float(hi & 0xFFFF0000u);
    asm("cvt.rn.bf16x2.f32 %0, %1, %2;" : "=r"(lo) : "f"(ry), "f"(rx));
}

// m16n8k16 row.col bf16 HMMA, D=C in-place
__device__ __forceinline__ void mma_bf16(float *d, const uint32_t *a,
                                         const uint32_t *b) {
    asm volatile(
        "mma.sync.aligned.m16n8k16.row.col.f32.bf16.bf16.f32 "
        "{%0,%1,%2,%3}, {%4,%5,%6,%7}, {%8,%9}, {%0,%1,%2,%3};"
        : "+f"(d[0]), "+f"(d[1]), "+f"(d[2]), "+f"(d[3])
        : "r"(a[0]), "r"(a[1]), "r"(a[2]), "r"(a[3]), "r"(b[0]), "r"(b[1]));
}

// ---------------------------------------------------------------------------
// Kernel 1: conv 3x3 SAME + bias + relu + maxpool 2x2  (unchanged)
// ---------------------------------------------------------------------------
__global__ void __launch_bounds__(256) conv_pool_kernel(
    const float *__restrict__ x, const float *__restrict__ cw,
    const float *__restrict__ cb)
{
    __shared__ float sin_[3][34][34];
    __shared__ float wp[27 * 32];
    __shared__ float bb[32];

    int t = threadIdx.x;
    int b = blockIdx.y;
    int tpy = (blockIdx.x >> 2) * 16, tpx = (blockIdx.x & 3) * 16;

    for (int i = t; i < 864; i += 256) {
        int co = i / 27, rem = i % 27;
        wp[rem * 32 + co] = cw[i];
    }
    if (t < 32) bb[t] = cb[t];

    int oy = 2 * tpy - 1, ox = 2 * tpx - 1;
    for (int i = t; i < 3 * 34 * 34; i += 256) {
        int ci = i / 1156, rem = i % 1156, iy = rem / 34, ix = rem % 34;
        int gy = oy + iy, gx = ox + ix;
        float v = 0.f;
        if (gy >= 0 && gy < 128 && gx >= 0 && gx < 128)
            v = x[((b * 3 + ci) * 128 + gy) * 128 + gx];
        sin_[ci][iy][ix] = v;
    }
    __syncthreads();

    int py = t >> 4, px = t & 15;
    float in[3][4][4];
#pragma unroll
    for (int ci = 0; ci < 3; ci++)
#pragma unroll
        for (int r = 0; r < 4; r++)
#pragma unroll
            for (int c = 0; c < 4; c++)
                in[ci][r][c] = sin_[ci][2 * py + r][2 * px + c];

    const float2 *wp2 = reinterpret_cast<const float2 *>(wp);
    int gy = tpy + py, gx = tpx + px;
    float *outb = d_pool_buf + (size_t)b * 131072;

#pragma unroll
    for (int g = 0; g < 4; g++) {
        float2 acc[2][2][4];
#pragma unroll
        for (int dy = 0; dy < 2; dy++)
#pragma unroll
            for (int dx = 0; dx < 2; dx++)
#pragma unroll
                for (int p = 0; p < 4; p++) acc[dy][dx][p] = make_float2(0.f, 0.f);

#pragma unroll
        for (int ci = 0; ci < 3; ci++)
#pragma unroll
            for (int ky = 0; ky < 3; ky++)
#pragma unroll
                for (int kx = 0; kx < 3; kx++) {
                    int tap = ci * 9 + ky * 3 + kx;
                    float2 w0 = wp2[tap * 16 + g * 4 + 0];
                    float2 w1 = wp2[tap * 16 + g * 4 + 1];
                    float2 w2 = wp2[tap * 16 + g * 4 + 2];
                    float2 w3 = wp2[tap * 16 + g * 4 + 3];
#pragma unroll
                    for (int dy = 0; dy < 2; dy++)
#pragma unroll
                        for (int dx = 0; dx < 2; dx++) {
                            float iv = in[ci][dy + ky][dx + kx];
                            float2 iv2 = make_float2(iv, iv);
                            fma2(acc[dy][dx][0], iv2, w0);
                            fma2(acc[dy][dx][1], iv2, w1);
                            fma2(acc[dy][dx][2], iv2, w2);
                            fma2(acc[dy][dx][3], iv2, w3);
                        }
                }
#pragma unroll
        for (int p = 0; p < 4; p++) {
            int co = g * 8 + p * 2;
            float mx = fmaxf(fmaxf(acc[0][0][p].x, acc[0][1][p].x),
                             fmaxf(acc[1][0][p].x, acc[1][1][p].x));
            float my = fmaxf(fmaxf(acc[0][0][p].y, acc[0][1][p].y),
                             fmaxf(acc[1][0][p].y, acc[1][1][p].y));
            mx = fmaxf(mx + bb[co], 0.f);
            my = fmaxf(my + bb[co + 1], 0.f);
            outb[(co * 64 + gy) * 64 + gx] = mx;
            outb[((co + 1) * 64 + gy) * 64 + gx] = my;
        }
    }
}

// ---------------------------------------------------------------------------
// Kernel 2: GCN (stencil + x32->64 GEMM); epilogue now emits bf16 hi/lo G.
// ---------------------------------------------------------------------------
__device__ __forceinline__ float dinvf(int r, int c) {
    int deg = 1 + (r > 0) + (r < 63) + (c > 0) + (c < 63);
    return rsqrtf((float)deg);
}

__global__ void __launch_bounds__(256) gcn_kernel(
    const float *__restrict__ gw, const float *__restrict__ gb)
{
    extern __shared__ float sm[];
    float *aggx = sm;            // [512][36]
    float *wg = sm + 512 * 36;   // [32][64]
    float *bg = wg + 2048;       // [64]

    int t = threadIdx.x, b = blockIdx.y;
    int node0 = blockIdx.x * 512;

    for (int i = t; i < 2048; i += 256) wg[i] = gw[i];
    if (t < 64) bg[t] = gb[t];

    const float *nf = d_pool_buf + (size_t)b * 131072;
    int q = t & 7, ns = t >> 3;
#pragma unroll 4
    for (int i = 0; i < 16; i++) {
        int nl = ns + 32 * i;
        int n = node0 + nl;
        int r = n >> 6, c = n & 63;
        float dn = dinvf(r, c);
        const float4 *base = reinterpret_cast<const float4 *>(nf) + n * 8 + q;
        float4 v = __ldg(base);
        float4 a;
        a.x = dn * v.x; a.y = dn * v.y; a.z = dn * v.z; a.w = dn * v.w;
        if (r > 0) {
            float s = dinvf(r - 1, c); float4 u = __ldg(base - 512);
            a.x += s * u.x; a.y += s * u.y; a.z += s * u.z; a.w += s * u.w;
        }
        if (r < 63) {
            float s = dinvf(r + 1, c); float4 u = __ldg(base + 512);
            a.x += s * u.x; a.y += s * u.y; a.z += s * u.z; a.w += s * u.w;
        }
        if (c > 0) {
            float s = dinvf(r, c - 1); float4 u = __ldg(base - 8);
            a.x += s * u.x; a.y += s * u.y; a.z += s * u.z; a.w += s * u.w;
        }
        if (c < 63) {
            float s = dinvf(r, c + 1); float4 u = __ldg(base + 8);
            a.x += s * u.x; a.y += s * u.y; a.z += s * u.z; a.w += s * u.w;
        }
        a.x *= dn; a.y *= dn; a.z *= dn; a.w *= dn;
        *reinterpret_cast<float4 *>(&aggx[nl * 36 + q * 4]) = a;
    }
    __syncthreads();

    int ot = t & 7, ng = t >> 3;
    const float4 *wg4 = reinterpret_cast<const float4 *>(wg);
    uint32_t *ghi = reinterpret_cast<uint32_t *>(d_g_hi) + (size_t)b * 131072;
    uint32_t *glo = reinterpret_cast<uint32_t *>(d_g_lo) + (size_t)b * 131072;
#pragma unroll
    for (int it = 0; it < 2; it++) {
        int nb = (it * 32 + ng) * 8;
        float2 acc[8][4];
#pragma unroll
        for (int i = 0; i < 8; i++)
#pragma unroll
            for (int p = 0; p < 4; p++) acc[i][p] = make_float2(0.f, 0.f);

#pragma unroll 4
        for (int f = 0; f < 32; f++) {
            float4 wA = wg4[f * 16 + ot * 2];
            float4 wB = wg4[f * 16 + ot * 2 + 1];
            float2 p0 = make_float2(wA.x, wA.y), p1 = make_float2(wA.z, wA.w);
            float2 p2 = make_float2(wB.x, wB.y), p3 = make_float2(wB.z, wB.w);
#pragma unroll
            for (int i = 0; i < 8; i++) {
                float av = aggx[(nb + i) * 36 + f];
                float2 ad = make_float2(av, av);
                fma2(acc[i][0], ad, p0);
                fma2(acc[i][1], ad, p1);
                fma2(acc[i][2], ad, p2);
                fma2(acc[i][3], ad, p3);
            }
        }
#pragma unroll
        for (int i = 0; i < 8; i++) {
            int ubase = (node0 + nb + i) * 32 + ot * 4;
#pragma unroll
            for (int p = 0; p < 4; p++) {
                float2 v;
                v.x = fmaxf(acc[i][p].x + bg[ot * 8 + 2 * p], 0.f);
                v.y = fmaxf(acc[i][p].y + bg[ot * 8 + 2 * p + 1], 0.f);
                uint32_t hi, lo;
                cvt_hilo(v, hi, lo);
                ghi[ubase + p] = hi;
                glo[ubase + p] = lo;
            }
        }
    }
}

// ---------------------------------------------------------------------------
// Dummy kernel: keeps fc1_kernel as the 4th launch (ncu profiles launch #4).
// ---------------------------------------------------------------------------
__global__ void nop_kernel() {}

// ---------------------------------------------------------------------------
// Kernel 3: FC1 streaming HMMA GEMM. 512 CTAs (3/SM) x 256 threads, K=512 per
// CTA. G bf16 hi/lo k-slice TMA-staged ONCE into padded smem rows (1040B ->
// conflict-free LDS.32 B fragments). W fragments streamed via __ldg float2,
// converted to bf16 hi/lo in regs; 12 HMMA per k16 (AhBh + AhBl + AlBh).
// No barriers inside the k loop.
// ---------------------------------------------------------------------------
#define FC1_KSLICE 512
#define GROW_U32 260                     // uint32 words per padded G row
#define G_LO_OFF (32 * GROW_U32)         // uint32 offset of lo plane
#define FC1_SMEM (2 * 32 * GROW_U32 * 4 + 16)  // 66576 B

__global__ void __launch_bounds__(256, 3) fc1_kernel(const float *__restrict__ w1)
{
    extern __shared__ uint32_t smg[];
    uint32_t sb = s2u(smg);
    uint32_t mb = sb + 2 * 32 * GROW_U32 * 4;
    int t = threadIdx.x, lane = t & 31, w = t >> 5;
    int bi = blockIdx.x;
    int kstart = bi * FC1_KSLICE;

    if (t == 0) mbar_init(mb, 32);
    __syncthreads();
    if (t < 32) {
        mbar_expect_tx(mb, 2048);
        bulk_cp(sb + lane * (GROW_U32 * 4),
                d_g_hi + (size_t)lane * K_FC + kstart, FC1_KSLICE * 2, mb);
        bulk_cp(sb + G_LO_OFF * 4 + lane * (GROW_U32 * 4),
                d_g_lo + (size_t)lane * K_FC + kstart, FC1_KSLICE * 2, mb);
    }
    mbar_wait(mb, 0);

    float acc[4][4];
#pragma unroll
    for (int nt = 0; nt < 4; nt++)
#pragma unroll
        for (int p = 0; p < 4; p++) acc[nt][p] = 0.f;

    int q = lane >> 2, kc2 = lane & 3;   // fragment coords; kc = 2*kc2
    int mbase = 16 * w;
    const float *wb0 = w1 + (size_t)(mbase + q) * K_FC + kstart + kc2 * 2;
    const float *wb1 = wb0 + (size_t)8 * K_FC;

#pragma unroll 2
    for (int ks = 0; ks < FC1_KSLICE / 16; ks++) {
        float2 fa0 = __ldg(reinterpret_cast<const float2 *>(wb0 + ks * 16));
        float2 fa1 = __ldg(reinterpret_cast<const float2 *>(wb1 + ks * 16));
        float2 fa2 = __ldg(reinterpret_cast<const float2 *>(wb0 + ks * 16 + 8));
        float2 fa3 = __ldg(reinterpret_cast<const float2 *>(wb1 + ks * 16 + 8));
        uint32_t Ah[4], Al[4];
        cvt_hilo(fa0, Ah[0], Al[0]);
        cvt_hilo(fa1, Ah[1], Al[1]);
        cvt_hilo(fa2, Ah[2], Al[2]);
        cvt_hilo(fa3, Ah[3], Al[3]);

        int wq = ks * 8 + kc2;
#pragma unroll
        for (int nt = 0; nt < 4; nt++) {
            int n = nt * 8 + q;
            uint32_t bh[2], bl[2];
            bh[0] = smg[n * GROW_U32 + wq];
            bh[1] = smg[n * GROW_U32 + wq + 4];
            bl[0] = smg[G_LO_OFF + n * GROW_U32 + wq];
            bl[1] = smg[G_LO_OFF + n * GROW_U32 + wq + 4];
            mma_bf16(acc[nt], Ah, bh);
            mma_bf16(acc[nt], Ah, bl);
            mma_bf16(acc[nt], Al, bh);
        }
    }

    float *pp = d_part_buf + (size_t)bi * 4096;
    int cb = kc2 * 2;
#pragma unroll
    for (int nt = 0; nt < 4; nt++) {
        int n0 = nt * 8 + cb;
        pp[(n0    ) * 128 + mbase + q    ] = acc[nt][0];
        pp[(n0 + 1) * 128 + mbase + q    ] = acc[nt][1];
        pp[(n0    ) * 128 + mbase + q + 8] = acc[nt][2];
        pp[(n0 + 1) * 128 + mbase + q + 8] = acc[nt][3];
    }
}

// ---------------------------------------------------------------------------
// Kernel 4a: reduce 512 partial sets -> relu(f1 + b1).  grid (32 b, 4 jq)
// ---------------------------------------------------------------------------
__global__ void __launch_bounds__(1024) fc1_reduce_kernel(const float *__restrict__ f1b)
{
    __shared__ float red[32][33];
    int t = threadIdx.x, b = blockIdx.x, jq = blockIdx.y;
    int jl = t & 31, sg = t >> 5;
    int j = jq * 32 + jl;

    const float *pp = d_part_buf + b * 128 + j;
    float ssum = 0.f;
    for (int i = sg; i < 512; i += 32) ssum += pp[(size_t)i * 4096];
    red[sg][jl] = ssum;
    __syncthreads();

    if (t < 32) {
        float v = 0.f;
#pragma unroll
        for (int u = 0; u < 32; u++) v += red[u][t];
        int jo = jq * 32 + t;
        d_f1_buf[b * 128 + jo] = fmaxf(v + f1b[jo], 0.f);
    }
}

// ---------------------------------------------------------------------------
// Kernel 4b: FC2 (101 x 128) + bias.  grid 32 (one block per batch)
// ---------------------------------------------------------------------------
__global__ void __launch_bounds__(128) fc2_kernel(
    const float *__restrict__ w2, const float *__restrict__ b2,
    float *__restrict__ out)
{
    __shared__ float f1s[128];
    int t = threadIdx.x, b = blockIdx.x;
    f1s[t] = d_f1_buf[b * 128 + t];
    __syncthreads();

    if (t < 101) {
        float acc = b2[t];
        const float *wr = w2 + t * 128;
#pragma unroll 8
        for (int jj = 0; jj < 128; jj++) acc = fmaf(f1s[jj], __ldg(&wr[jj]), acc);
        out[b * 101 + t] = acc;
    }
}

// ---------------------------------------------------------------------------
extern "C" void kernel_launch(void *const *d_in, const int *in_sizes, int n_in,
                              void *d_out, int out_size)
{
    (void)in_sizes; (void)n_in; (void)out_size;
    const float *x  = (const float *)d_in[0];
    const float *cw = (const float *)d_in[1];
    const float *cb = (const float *)d_in[2];
    const float *gw = (const float *)d_in[3];
    const float *gb = (const float *)d_in[4];
    const float *w1 = (const float *)d_in[5];
    const float *b1 = (const float *)d_in[6];
    const float *w2 = (const float *)d_in[7];
    const float *b2 = (const float *)d_in[8];
    float *out = (float *)d_out;

    const int gcn_smem = (512 * 36 + 2048 + 64) * 4;  // 82176 B
    cudaFuncSetAttribute(gcn_kernel, cudaFuncAttributeMaxDynamicSharedMemorySize, gcn_smem);
    cudaFuncSetAttribute(fc1_kernel, cudaFuncAttributeMaxDynamicSharedMemorySize, FC1_SMEM);

    conv_pool_kernel<<<dim3(16, 32), 256>>>(x, cw, cb);   // launch 1
    gcn_kernel<<<dim3(8, 32), 256, gcn_smem>>>(gw, gb);   // launch 2
    nop_kernel<<<1, 32>>>();                              // launch 3 (profiling align)
    fc1_kernel<<<512, 256, FC1_SMEM>>>(w1);               // launch 4 <- ncu target
    fc1_reduce_kernel<<<dim3(32, 4), 1024>>>(b1);         // launch 5
    fc2_kernel<<<32, 128>>>(w2, b2, out);                 // launch 6
}

// round 9
// speedup vs baseline: 1.3625x; 1.0843x over previous
#include <cuda_runtime.h>
#include <cstdint>

// ---------------------------------------------------------------------------
// PartBasedGraphCNN: conv3x3(3->32)+relu+pool2 -> grid-GCN(32->64) -> FC1 -> FC2
// FC1 = bf16-split HMMA GEMM, streaming W via __ldg, G pre-converted bf16
// hi/lo by GCN (now uint4-coalesced), TMA-staged once per CTA.
// ---------------------------------------------------------------------------

#define K_FC 262144  // 4096 nodes * 64 feats

__device__ float d_pool_buf[32 * 32 * 64 * 64];       // [B][32][64][64] 16.8 MB
__device__ uint16_t d_g_hi[32u * 262144u];            // [B][K] bf16 hi  16.8 MB
__device__ uint16_t d_g_lo[32u * 262144u];            // [B][K] bf16 lo  16.8 MB
__device__ float d_part_buf[512 * 32 * 128];          // [set][B][128]    8.4 MB
__device__ float d_f1_buf[32 * 128];                  // [B][128]

__device__ __forceinline__ void fma2(float2 &d, const float2 a, const float2 b) {
    asm("fma.rn.f32x2 %0, %1, %2, %0;"
        : "+l"(*reinterpret_cast<unsigned long long *>(&d))
        : "l"(*reinterpret_cast<const unsigned long long *>(&a)),
          "l"(*reinterpret_cast<const unsigned long long *>(&b)));
}

__device__ __forceinline__ uint32_t s2u(const void *p) {
    return (uint32_t)__cvta_generic_to_shared(p);
}

__device__ __forceinline__ void bulk_cp(uint32_t dst_smem, const void *src_gmem,
                                        uint32_t bytes, uint32_t mbar) {
    asm volatile(
        "cp.async.bulk.shared::cta.global.mbarrier::complete_tx::bytes "
        "[%0], [%1], %2, [%3];"
        :: "r"(dst_smem), "l"(src_gmem), "r"(bytes), "r"(mbar) : "memory");
}

__device__ __forceinline__ void mbar_init(uint32_t mbar, uint32_t count) {
    asm volatile("mbarrier.init.shared::cta.b64 [%0], %1;" :: "r"(mbar), "r"(count));
}

__device__ __forceinline__ void mbar_expect_tx(uint32_t mbar, uint32_t bytes) {
    asm volatile("mbarrier.arrive.expect_tx.shared::cta.b64 _, [%0], %1;"
                 :: "r"(mbar), "r"(bytes) : "memory");
}

__device__ __forceinline__ void mbar_wait(uint32_t mbar, uint32_t parity) {
    asm volatile(
        "{\n\t"
        ".reg .pred P;\n\t"
        "WAIT_%=:\n\t"
        "mbarrier.try_wait.parity.acquire.cta.shared::cta.b64 P, [%0], %1, 0x989680;\n\t"
        "@P bra.uni DONE_%=;\n\t"
        "bra.uni WAIT_%=;\n\t"
        "DONE_%=:\n\t"
        "}"
        :: "r"(mbar), "r"(parity) : "memory");
}

// fp32 pair -> bf16x2 hi + bf16x2 lo (residual). lo half of reg = even elem.
__device__ __forceinline__ void cvt_hilo(float2 f, uint32_t &hi, uint32_t &lo) {
    asm("cvt.rn.bf16x2.f32 %0, %1, %2;" : "=r"(hi) : "f"(f.y), "f"(f.x));
    float rx = f.x - __uint_as_float(hi << 16);
    float ry = f.y - __uint_as_float(hi & 0xFFFF0000u);
    asm("cvt.rn.bf16x2.f32 %0, %1, %2;" : "=r"(lo) : "f"(ry), "f"(rx));
}

// m16n8k16 row.col bf16 HMMA, D=C in-place
__device__ __forceinline__ void mma_bf16(float *d, const uint32_t *a,
                                         const uint32_t *b) {
    asm volatile(
        "mma.sync.aligned.m16n8k16.row.col.f32.bf16.bf16.f32 "
        "{%0,%1,%2,%3}, {%4,%5,%6,%7}, {%8,%9}, {%0,%1,%2,%3};"
        : "+f"(d[0]), "+f"(d[1]), "+f"(d[2]), "+f"(d[3])
        : "r"(a[0]), "r"(a[1]), "r"(a[2]), "r"(a[3]), "r"(b[0]), "r"(b[1]));
}

// ---------------------------------------------------------------------------
// Kernel 1: conv 3x3 SAME + bias + relu + maxpool 2x2  (unchanged)
// ---------------------------------------------------------------------------
__global__ void __launch_bounds__(256) conv_pool_kernel(
    const float *__restrict__ x, const float *__restrict__ cw,
    const float *__restrict__ cb)
{
    __shared__ float sin_[3][34][34];
    __shared__ float wp[27 * 32];
    __shared__ float bb[32];

    int t = threadIdx.x;
    int b = blockIdx.y;
    int tpy = (blockIdx.x >> 2) * 16, tpx = (blockIdx.x & 3) * 16;

    for (int i = t; i < 864; i += 256) {
        int co = i / 27, rem = i % 27;
        wp[rem * 32 + co] = cw[i];
    }
    if (t < 32) bb[t] = cb[t];

    int oy = 2 * tpy - 1, ox = 2 * tpx - 1;
    for (int i = t; i < 3 * 34 * 34; i += 256) {
        int ci = i / 1156, rem = i % 1156, iy = rem / 34, ix = rem % 34;
        int gy = oy + iy, gx = ox + ix;
        float v = 0.f;
        if (gy >= 0 && gy < 128 && gx >= 0 && gx < 128)
            v = x[((b * 3 + ci) * 128 + gy) * 128 + gx];
        sin_[ci][iy][ix] = v;
    }
    __syncthreads();

    int py = t >> 4, px = t & 15;
    float in[3][4][4];
#pragma unroll
    for (int ci = 0; ci < 3; ci++)
#pragma unroll
        for (int r = 0; r < 4; r++)
#pragma unroll
            for (int c = 0; c < 4; c++)
                in[ci][r][c] = sin_[ci][2 * py + r][2 * px + c];

    const float2 *wp2 = reinterpret_cast<const float2 *>(wp);
    int gy = tpy + py, gx = tpx + px;
    float *outb = d_pool_buf + (size_t)b * 131072;

#pragma unroll
    for (int g = 0; g < 4; g++) {
        float2 acc[2][2][4];
#pragma unroll
        for (int dy = 0; dy < 2; dy++)
#pragma unroll
            for (int dx = 0; dx < 2; dx++)
#pragma unroll
                for (int p = 0; p < 4; p++) acc[dy][dx][p] = make_float2(0.f, 0.f);

#pragma unroll
        for (int ci = 0; ci < 3; ci++)
#pragma unroll
            for (int ky = 0; ky < 3; ky++)
#pragma unroll
                for (int kx = 0; kx < 3; kx++) {
                    int tap = ci * 9 + ky * 3 + kx;
                    float2 w0 = wp2[tap * 16 + g * 4 + 0];
                    float2 w1 = wp2[tap * 16 + g * 4 + 1];
                    float2 w2 = wp2[tap * 16 + g * 4 + 2];
                    float2 w3 = wp2[tap * 16 + g * 4 + 3];
#pragma unroll
                    for (int dy = 0; dy < 2; dy++)
#pragma unroll
                        for (int dx = 0; dx < 2; dx++) {
                            float iv = in[ci][dy + ky][dx + kx];
                            float2 iv2 = make_float2(iv, iv);
                            fma2(acc[dy][dx][0], iv2, w0);
                            fma2(acc[dy][dx][1], iv2, w1);
                            fma2(acc[dy][dx][2], iv2, w2);
                            fma2(acc[dy][dx][3], iv2, w3);
                        }
                }
#pragma unroll
        for (int p = 0; p < 4; p++) {
            int co = g * 8 + p * 2;
            float mx = fmaxf(fmaxf(acc[0][0][p].x, acc[0][1][p].x),
                             fmaxf(acc[1][0][p].x, acc[1][1][p].x));
            float my = fmaxf(fmaxf(acc[0][0][p].y, acc[0][1][p].y),
                             fmaxf(acc[1][0][p].y, acc[1][1][p].y));
            mx = fmaxf(mx + bb[co], 0.f);
            my = fmaxf(my + bb[co + 1], 0.f);
            outb[(co * 64 + gy) * 64 + gx] = mx;
            outb[((co + 1) * 64 + gy) * 64 + gx] = my;
        }
    }
}

// ---------------------------------------------------------------------------
// Kernel 2: GCN (stencil + x32->64 GEMM); bf16 hi/lo epilogue with uint4
// (STG.128) fully-coalesced stores.
// ---------------------------------------------------------------------------
__device__ __forceinline__ float dinvf(int r, int c) {
    int deg = 1 + (r > 0) + (r < 63) + (c > 0) + (c < 63);
    return rsqrtf((float)deg);
}

__global__ void __launch_bounds__(256) gcn_kernel(
    const float *__restrict__ gw, const float *__restrict__ gb)
{
    extern __shared__ float sm[];
    float *aggx = sm;            // [512][36]
    float *wg = sm + 512 * 36;   // [32][64]
    float *bg = wg + 2048;       // [64]

    int t = threadIdx.x, b = blockIdx.y;
    int node0 = blockIdx.x * 512;

    for (int i = t; i < 2048; i += 256) wg[i] = gw[i];
    if (t < 64) bg[t] = gb[t];

    const float *nf = d_pool_buf + (size_t)b * 131072;
    int q = t & 7, ns = t >> 3;
#pragma unroll 4
    for (int i = 0; i < 16; i++) {
        int nl = ns + 32 * i;
        int n = node0 + nl;
        int r = n >> 6, c = n & 63;
        float dn = dinvf(r, c);
        const float4 *base = reinterpret_cast<const float4 *>(nf) + n * 8 + q;
        float4 v = __ldg(base);
        float4 a;
        a.x = dn * v.x; a.y = dn * v.y; a.z = dn * v.z; a.w = dn * v.w;
        if (r > 0) {
            float s = dinvf(r - 1, c); float4 u = __ldg(base - 512);
            a.x += s * u.x; a.y += s * u.y; a.z += s * u.z; a.w += s * u.w;
        }
        if (r < 63) {
            float s = dinvf(r + 1, c); float4 u = __ldg(base + 512);
            a.x += s * u.x; a.y += s * u.y; a.z += s * u.z; a.w += s * u.w;
        }
        if (c > 0) {
            float s = dinvf(r, c - 1); float4 u = __ldg(base - 8);
            a.x += s * u.x; a.y += s * u.y; a.z += s * u.z; a.w += s * u.w;
        }
        if (c < 63) {
            float s = dinvf(r, c + 1); float4 u = __ldg(base + 8);
            a.x += s * u.x; a.y += s * u.y; a.z += s * u.z; a.w += s * u.w;
        }
        a.x *= dn; a.y *= dn; a.z *= dn; a.w *= dn;
        *reinterpret_cast<float4 *>(&aggx[nl * 36 + q * 4]) = a;
    }
    __syncthreads();

    int ot = t & 7, ng = t >> 3;
    const float4 *wg4 = reinterpret_cast<const float4 *>(wg);
    uint32_t *ghi = reinterpret_cast<uint32_t *>(d_g_hi) + (size_t)b * 131072;
    uint32_t *glo = reinterpret_cast<uint32_t *>(d_g_lo) + (size_t)b * 131072;
#pragma unroll
    for (int it = 0; it < 2; it++) {
        int nb = (it * 32 + ng) * 8;
        float2 acc[8][4];
#pragma unroll
        for (int i = 0; i < 8; i++)
#pragma unroll
            for (int p = 0; p < 4; p++) acc[i][p] = make_float2(0.f, 0.f);

#pragma unroll 4
        for (int f = 0; f < 32; f++) {
            float4 wA = wg4[f * 16 + ot * 2];
            float4 wB = wg4[f * 16 + ot * 2 + 1];
            float2 p0 = make_float2(wA.x, wA.y), p1 = make_float2(wA.z, wA.w);
            float2 p2 = make_float2(wB.x, wB.y), p3 = make_float2(wB.z, wB.w);
#pragma unroll
            for (int i = 0; i < 8; i++) {
                float av = aggx[(nb + i) * 36 + f];
                float2 ad = make_float2(av, av);
                fma2(acc[i][0], ad, p0);
                fma2(acc[i][1], ad, p1);
                fma2(acc[i][2], ad, p2);
                fma2(acc[i][3], ad, p3);
            }
        }
#pragma unroll
        for (int i = 0; i < 8; i++) {
            int ubase = (node0 + nb + i) * 32 + ot * 4;
            uint4 H, L;
            float2 v;
            v.x = fmaxf(acc[i][0].x + bg[ot * 8 + 0], 0.f);
            v.y = fmaxf(acc[i][0].y + bg[ot * 8 + 1], 0.f);
            cvt_hilo(v, H.x, L.x);
            v.x = fmaxf(acc[i][1].x + bg[ot * 8 + 2], 0.f);
            v.y = fmaxf(acc[i][1].y + bg[ot * 8 + 3], 0.f);
            cvt_hilo(v, H.y, L.y);
            v.x = fmaxf(acc[i][2].x + bg[ot * 8 + 4], 0.f);
            v.y = fmaxf(acc[i][2].y + bg[ot * 8 + 5], 0.f);
            cvt_hilo(v, H.z, L.z);
            v.x = fmaxf(acc[i][3].x + bg[ot * 8 + 6], 0.f);
            v.y = fmaxf(acc[i][3].y + bg[ot * 8 + 7], 0.f);
            cvt_hilo(v, H.w, L.w);
            *reinterpret_cast<uint4 *>(ghi + ubase) = H;
            *reinterpret_cast<uint4 *>(glo + ubase) = L;
        }
    }
}

// ---------------------------------------------------------------------------
// Dummy kernel: alignment so gcn_kernel is launch #4 (the profiled slot).
// ---------------------------------------------------------------------------
__global__ void nop_kernel() {}

// ---------------------------------------------------------------------------
// Kernel 3: FC1 streaming HMMA GEMM. 512 CTAs (3/SM) x 256 threads, K=512 per
// CTA. G bf16 hi/lo staged once; W streamed via __ldg float2 (unroll 4 ->
// ~16 LDGs in flight/thread); 12 HMMA per k16 (AhBh + AhBl + AlBh).
// ---------------------------------------------------------------------------
#define FC1_KSLICE 512
#define GROW_U32 260                     // uint32 words per padded G row
#define G_LO_OFF (32 * GROW_U32)         // uint32 offset of lo plane
#define FC1_SMEM (2 * 32 * GROW_U32 * 4 + 16)  // 66576 B

__global__ void __launch_bounds__(256, 3) fc1_kernel(const float *__restrict__ w1)
{
    extern __shared__ uint32_t smg[];
    uint32_t sb = s2u(smg);
    uint32_t mb = sb + 2 * 32 * GROW_U32 * 4;
    int t = threadIdx.x, lane = t & 31, w = t >> 5;
    int bi = blockIdx.x;
    int kstart = bi * FC1_KSLICE;

    if (t == 0) mbar_init(mb, 32);
    __syncthreads();
    if (t < 32) {
        mbar_expect_tx(mb, 2048);
        bulk_cp(sb + lane * (GROW_U32 * 4),
                d_g_hi + (size_t)lane * K_FC + kstart, FC1_KSLICE * 2, mb);
        bulk_cp(sb + G_LO_OFF * 4 + lane * (GROW_U32 * 4),
                d_g_lo + (size_t)lane * K_FC + kstart, FC1_KSLICE * 2, mb);
    }
    mbar_wait(mb, 0);

    float acc[4][4];
#pragma unroll
    for (int nt = 0; nt < 4; nt++)
#pragma unroll
        for (int p = 0; p < 4; p++) acc[nt][p] = 0.f;

    int q = lane >> 2, kc2 = lane & 3;   // fragment coords; kc = 2*kc2
    int mbase = 16 * w;
    const float *wb0 = w1 + (size_t)(mbase + q) * K_FC + kstart + kc2 * 2;
    const float *wb1 = wb0 + (size_t)8 * K_FC;

#pragma unroll 4
    for (int ks = 0; ks < FC1_KSLICE / 16; ks++) {
        float2 fa0 = __ldg(reinterpret_cast<const float2 *>(wb0 + ks * 16));
        float2 fa1 = __ldg(reinterpret_cast<const float2 *>(wb1 + ks * 16));
        float2 fa2 = __ldg(reinterpret_cast<const float2 *>(wb0 + ks * 16 + 8));
        float2 fa3 = __ldg(reinterpret_cast<const float2 *>(wb1 + ks * 16 + 8));
        uint32_t Ah[4], Al[4];
        cvt_hilo(fa0, Ah[0], Al[0]);
        cvt_hilo(fa1, Ah[1], Al[1]);
        cvt_hilo(fa2, Ah[2], Al[2]);
        cvt_hilo(fa3, Ah[3], Al[3]);

        int wq = ks * 8 + kc2;
#pragma unroll
        for (int nt = 0; nt < 4; nt++) {
            int n = nt * 8 + q;
            uint32_t bh[2], bl[2];
            bh[0] = smg[n * GROW_U32 + wq];
            bh[1] = smg[n * GROW_U32 + wq + 4];
            bl[0] = smg[G_LO_OFF + n * GROW_U32 + wq];
            bl[1] = smg[G_LO_OFF + n * GROW_U32 + wq + 4];
            mma_bf16(acc[nt], Ah, bh);
            mma_bf16(acc[nt], Ah, bl);
            mma_bf16(acc[nt], Al, bh);
        }
    }

    float *pp = d_part_buf + (size_t)bi * 4096;
    int cb = kc2 * 2;
#pragma unroll
    for (int nt = 0; nt < 4; nt++) {
        int n0 = nt * 8 + cb;
        pp[(n0    ) * 128 + mbase + q    ] = acc[nt][0];
        pp[(n0 + 1) * 128 + mbase + q    ] = acc[nt][1];
        pp[(n0    ) * 128 + mbase + q + 8] = acc[nt][2];
        pp[(n0 + 1) * 128 + mbase + q + 8] = acc[nt][3];
    }
}

// ---------------------------------------------------------------------------
// Kernel 4a: reduce 512 partial sets -> relu(f1 + b1).  grid (32 b, 4 jq)
// ---------------------------------------------------------------------------
__global__ void __launch_bounds__(1024) fc1_reduce_kernel(const float *__restrict__ f1b)
{
    __shared__ float red[32][33];
    int t = threadIdx.x, b = blockIdx.x, jq = blockIdx.y;
    int jl = t & 31, sg = t >> 5;
    int j = jq * 32 + jl;

    const float *pp = d_part_buf + b * 128 + j;
    float ssum = 0.f;
    for (int i = sg; i < 512; i += 32) ssum += pp[(size_t)i * 4096];
    red[sg][jl] = ssum;
    __syncthreads();

    if (t < 32) {
        float v = 0.f;
#pragma unroll
        for (int u = 0; u < 32; u++) v += red[u][t];
        int jo = jq * 32 + t;
        d_f1_buf[b * 128 + jo] = fmaxf(v + f1b[jo], 0.f);
    }
}

// ---------------------------------------------------------------------------
// Kernel 4b: FC2 (101 x 128) + bias.  grid 32 (one block per batch)
// ---------------------------------------------------------------------------
__global__ void __launch_bounds__(128) fc2_kernel(
    const float *__restrict__ w2, const float *__restrict__ b2,
    float *__restrict__ out)
{
    __shared__ float f1s[128];
    int t = threadIdx.x, b = blockIdx.x;
    f1s[t] = d_f1_buf[b * 128 + t];
    __syncthreads();

    if (t < 101) {
        float acc = b2[t];
        const float *wr = w2 + t * 128;
#pragma unroll 8
        for (int jj = 0; jj < 128; jj++) acc = fmaf(f1s[jj], __ldg(&wr[jj]), acc);
        out[b * 101 + t] = acc;
    }
}

// ---------------------------------------------------------------------------
extern "C" void kernel_launch(void *const *d_in, const int *in_sizes, int n_in,
                              void *d_out, int out_size)
{
    (void)in_sizes; (void)n_in; (void)out_size;
    const float *x  = (const float *)d_in[0];
    const float *cw = (const float *)d_in[1];
    const float *cb = (const float *)d_in[2];
    const float *gw = (const float *)d_in[3];
    const float *gb = (const float *)d_in[4];
    const float *w1 = (const float *)d_in[5];
    const float *b1 = (const float *)d_in[6];
    const float *w2 = (const float *)d_in[7];
    const float *b2 = (const float *)d_in[8];
    float *out = (float *)d_out;

    const int gcn_smem = (512 * 36 + 2048 + 64) * 4;  // 82176 B
    cudaFuncSetAttribute(gcn_kernel, cudaFuncAttributeMaxDynamicSharedMemorySize, gcn_smem);
    cudaFuncSetAttribute(fc1_kernel, cudaFuncAttributeMaxDynamicSharedMemorySize, FC1_SMEM);

    conv_pool_kernel<<<dim3(16, 32), 256>>>(x, cw, cb);   // launch 1
    nop_kernel<<<1, 32>>>();                              // launch 2 (align)
    nop_kernel<<<1, 32>>>();                              // launch 3 (align)
    gcn_kernel<<<dim3(8, 32), 256, gcn_smem>>>(gw, gb);   // launch 4 <- ncu target
    fc1_kernel<<<512, 256, FC1_SMEM>>>(w1);               // launch 5
    fc1_reduce_kernel<<<dim3(32, 4), 1024>>>(b1);         // launch 6
    fc2_kernel<<<32, 128>>>(w2, b2, out);                 // launch 7
}